// round 3
// baseline (speedup 1.0000x reference)
#include <cuda_runtime.h>
#include <cstdint>
#include <cstddef>

// ---------------------------------------------------------------------------
// Transformer-XL relative attention, fp32 baseline.
//
// Shapes (fixed by the problem):
//   w   [4, 2048, 1024]   r [1, 2048, 1024]
//   r_w_bias / r_r_bias [16, 64]
//   Wq [1024,1024]  Wkv [1024,2048]  Wr [1024,1024]  Wo [1024,1024]
//   out [4, 1024, 1024] fp32
//
// rel_shift identity (derived from the reshape trick): for the unmasked
// region j <= i + 1024,  shift(BD)[b,i,j,n] = (q+rrb) . rk[j - i + 1023, n, :]
// ---------------------------------------------------------------------------

constexpr int BSZ = 4, QLEN = 1024, KLEN = 2048, NH = 16, DH = 64, DM = 1024;
constexpr int MEMLEN = KLEN - QLEN; // 1024

// Scratch (device globals: allocation-free rule)
__device__ float g_q [(size_t)BSZ * NH * QLEN * DH]; // [b,n,i,d] 16 MB
__device__ float g_k [(size_t)BSZ * NH * KLEN * DH]; // [b,n,j,d] 32 MB
__device__ float g_v [(size_t)BSZ * NH * KLEN * DH]; // [b,n,j,d] 32 MB
__device__ float g_rk[(size_t)NH * KLEN * DH];       // [n,drel,d] 8 MB
__device__ float g_av[(size_t)BSZ * QLEN * NH * DH]; // [b,i,n*64+d] 16 MB

// ---------------------------------------------------------------------------
// Generic 128x128 SGEMM, 256 threads, 8x8 per thread, K-step 16.
// MODE 0: q = w[:, -1024:] @ Wq      -> g_q  [b,n,i,d]
// MODE 1: kv = w @ Wkv (split)       -> g_k / g_v [b,n,j,d]
// MODE 2: rk = r @ Wr                -> g_rk [n,drel,d]
// MODE 3: out = g_av @ Wo            -> C (row-major [4096,1024])
// All M,N,K are multiples of 128 -> no bounds checks.
// ---------------------------------------------------------------------------
template <int MODE>
__global__ void __launch_bounds__(256, 2)
sgemm_k(const float* __restrict__ A, const float* __restrict__ B,
        float* __restrict__ C, int N, int K)
{
    __shared__ float As[16][132]; // [k][m] (transposed)
    __shared__ float Bs[16][128]; // [k][n]

    const int tid = threadIdx.x;
    const int m0  = blockIdx.y * 128;
    const int n0  = blockIdx.x * 128;
    const int tm0 = (tid >> 4) * 8;
    const int tn0 = (tid & 15) * 8;

    const float* Abase = (MODE == 3) ? g_av : A;

    float acc[8][8];
#pragma unroll
    for (int i = 0; i < 8; i++)
#pragma unroll
        for (int j = 0; j < 8; j++) acc[i][j] = 0.f;

    for (int kt = 0; kt < K; kt += 16) {
        // Load A tile (128 x 16), store transposed. 512 float4 / 256 thr.
#pragma unroll
        for (int t = 0; t < 2; t++) {
            int idx = tid * 2 + t;
            int rr  = idx >> 2;         // 0..127
            int kq  = (idx & 3) << 2;   // 0,4,8,12
            int row = m0 + rr;
            int grow = (MODE == 0) ? (((row >> 10) << 11) + QLEN + (row & (QLEN - 1)))
                                   : row;
            float4 a = *(const float4*)(Abase + (size_t)grow * K + kt + kq);
            As[kq + 0][rr] = a.x;
            As[kq + 1][rr] = a.y;
            As[kq + 2][rr] = a.z;
            As[kq + 3][rr] = a.w;
        }
        // Load B tile (16 x 128) directly.
#pragma unroll
        for (int t = 0; t < 2; t++) {
            int idx = tid * 2 + t;
            int rr  = idx >> 5;         // 0..15
            int cc  = (idx & 31) << 2;  // 0..124
            *(float4*)&Bs[rr][cc] =
                *(const float4*)(B + (size_t)(kt + rr) * N + n0 + cc);
        }
        __syncthreads();

#pragma unroll
        for (int k = 0; k < 16; k++) {
            float4 a0 = *(float4*)&As[k][tm0];
            float4 a1 = *(float4*)&As[k][tm0 + 4];
            float4 b0 = *(float4*)&Bs[k][tn0];
            float4 b1 = *(float4*)&Bs[k][tn0 + 4];
            float av[8] = {a0.x, a0.y, a0.z, a0.w, a1.x, a1.y, a1.z, a1.w};
            float bv[8] = {b0.x, b0.y, b0.z, b0.w, b1.x, b1.y, b1.z, b1.w};
#pragma unroll
            for (int i = 0; i < 8; i++)
#pragma unroll
                for (int j = 0; j < 8; j++)
                    acc[i][j] = fmaf(av[i], bv[j], acc[i][j]);
        }
        __syncthreads();
    }

    // Epilogue: scatter to target layout; 8 cols never straddle a 64-boundary.
#pragma unroll
    for (int i = 0; i < 8; i++) {
        int row = m0 + tm0 + i;
#pragma unroll
        for (int jq = 0; jq < 2; jq++) {
            int col = n0 + tn0 + jq * 4;
            float* dst;
            size_t idx;
            if (MODE == 0) {
                int b = row >> 10, i2 = row & 1023;
                int n = col >> 6, d = col & 63;
                dst = g_q;
                idx = (((size_t)(b * NH + n) * QLEN) + i2) * DH + d;
            } else if (MODE == 1) {
                int b = row >> 11, j = row & 2047;
                int cc = (col < DM) ? col : (col - DM);
                int n = cc >> 6, d = cc & 63;
                dst = (col < DM) ? g_k : g_v;
                idx = (((size_t)(b * NH + n) * KLEN) + j) * DH + d;
            } else if (MODE == 2) {
                int n = col >> 6, d = col & 63;
                dst = g_rk;
                idx = ((size_t)n * KLEN + row) * DH + d;
            } else {
                dst = C;
                idx = (size_t)row * N + col;
            }
            float4 v4 = make_float4(acc[i][jq * 4 + 0], acc[i][jq * 4 + 1],
                                    acc[i][jq * 4 + 2], acc[i][jq * 4 + 3]);
            *(float4*)(dst + idx) = v4;
        }
    }
}

// ---------------------------------------------------------------------------
// Fused flash-style relative attention.
// Grid: blockIdx.x = bh*16 + itile (bh = b*16+n, 16 i-tiles of 64 rows).
// Per j-tile (128 keys): S = (q+rwb)@K^T + diag-shift((q+rrb)@Rk^T), mask,
// online softmax, O += P@V.
// ---------------------------------------------------------------------------
constexpr int BI = 64, BJ = 128;
constexpr int QW_LD = 68, KS_LD = 132, RK_LD = 196, PT_LD = 68;
constexpr int SM_FLOATS = 64 * QW_LD * 2   // Qw,Qr (transposed [d][ii])
                        + 64 * KS_LD       // K^T  [d][jj]
                        + 64 * RK_LD       // Rk^T window [d][r], 192 rows
                        + 128 * 64         // V [jj][d]
                        + 128 * PT_LD;     // P^T [jj][ii]
constexpr int ATTN_SMEM_BYTES = SM_FLOATS * 4; // 186368 B

__global__ void __launch_bounds__(256, 1)
attn_kernel(const float* __restrict__ rwb, const float* __restrict__ rrb)
{
    extern __shared__ float sm[];
    float* Qw = sm;
    float* Qr = Qw + 64 * QW_LD;
    float* Ks = Qr + 64 * QW_LD;
    float* Rk = Ks + 64 * KS_LD;
    float* Vs = Rk + 64 * RK_LD;
    float* Pt = Vs + 128 * 64;

    const int tid  = threadIdx.x;
    const int rgrp = tid >> 4;   // 0..15 -> 4 query rows each
    const int cgrp = tid & 15;   // 0..15 -> 8 key cols each
    const int ii0  = rgrp * 4;
    const int jj0  = cgrp * 8;

    const int itile = blockIdx.x & 15;
    const int bh    = blockIdx.x >> 4;
    const int n     = bh & 15;
    const int b     = bh >> 4;
    const int i0    = itile * BI;

    const float* qbase = g_q  + (size_t)bh * QLEN * DH;
    const float* kbase = g_k  + (size_t)bh * KLEN * DH;
    const float* vbase = g_v  + (size_t)bh * KLEN * DH;
    const float* rkb   = g_rk + (size_t)n  * KLEN * DH;

    // Q tiles with both biases, transposed [d][ii]
    for (int e = tid; e < 64 * 64; e += 256) {
        int ii = e >> 6, d = e & 63;
        float qv = qbase[(size_t)(i0 + ii) * DH + d];
        Qw[d * QW_LD + ii] = qv + rwb[n * DH + d];
        Qr[d * QW_LD + ii] = qv + rrb[n * DH + d];
    }

    float O[4][4] = {};
    float mrow[4], lrow[4];
#pragma unroll
    for (int r2 = 0; r2 < 4; r2++) { mrow[r2] = -3.0e38f; lrow[r2] = 0.f; }

    // valid j for the tile's last row: i0+63+1024 -> cover with 128-wide tiles
    const int ntiles = (i0 + BI - 1 + MEMLEN + BJ) / BJ;
    const int rb = jj0 - ii0 + 60; // rk-window base row for this thread

    for (int t = 0; t < ntiles; t++) {
        const int j0 = t * BJ;
        __syncthreads(); // previous tile's Pt/Vs fully consumed

        for (int e = tid; e < 128 * 64; e += 256) {
            int jj = e >> 6, d = e & 63;
            Ks[d * KS_LD + jj] = kbase[(size_t)(j0 + jj) * DH + d];
        }
        for (int e = tid; e < 128 * 64; e += 256) {
            int jj = e >> 6, d = e & 63;
            Vs[jj * 64 + d] = vbase[(size_t)(j0 + jj) * DH + d];
        }
        // rk window: local row r <-> d_rel = dbase + r;  d_rel = j - i + 1023
        const int dbase = j0 - i0 + (QLEN - 1 - (BI - 1)); // j0 - i0 + 960
        for (int e = tid; e < 192 * 64; e += 256) {
            int rr = e >> 6, d = e & 63;
            int dr = dbase + rr;
            dr = dr < 0 ? 0 : (dr > KLEN - 1 ? KLEN - 1 : dr); // OOB rows are masked anyway
            Rk[d * RK_LD + rr] = rkb[(size_t)dr * DH + d];
        }
        __syncthreads();

        // --- scores: AC + shifted BD, per thread 4 rows x 8 cols ---
        float S[4][8];
#pragma unroll
        for (int rr = 0; rr < 4; rr++)
#pragma unroll
            for (int a = 0; a < 8; a++) S[rr][a] = 0.f;

#pragma unroll 8
        for (int k = 0; k < 64; k++) {
            float4 aw = *(float4*)&Qw[k * QW_LD + ii0];
            float4 ar = *(float4*)&Qr[k * QW_LD + ii0];
            float4 b0 = *(float4*)&Ks[k * KS_LD + jj0];
            float4 b1 = *(float4*)&Ks[k * KS_LD + jj0 + 4];
            float4 r0 = *(float4*)&Rk[k * RK_LD + rb];
            float4 r1 = *(float4*)&Rk[k * RK_LD + rb + 4];
            float4 r2 = *(float4*)&Rk[k * RK_LD + rb + 8];
            float awv[4] = {aw.x, aw.y, aw.z, aw.w};
            float arv[4] = {ar.x, ar.y, ar.z, ar.w};
            float bv[8]  = {b0.x, b0.y, b0.z, b0.w, b1.x, b1.y, b1.z, b1.w};
            float rv[12] = {r0.x, r0.y, r0.z, r0.w, r1.x, r1.y, r1.z, r1.w,
                            r2.x, r2.y, r2.z, r2.w};
#pragma unroll
            for (int rr = 0; rr < 4; rr++)
#pragma unroll
                for (int a = 0; a < 8; a++)
                    // window row (jj-ii+63) - rb = a - rr + 3  (compile-time)
                    S[rr][a] = fmaf(awv[rr], bv[a],
                               fmaf(arv[rr], rv[a - rr + 3], S[rr][a]));
        }

        // --- scale, mask, online softmax ---
        const float scale = 0.125f; // 1/sqrt(64)
#pragma unroll
        for (int rr = 0; rr < 4; rr++) {
            int gi = i0 + ii0 + rr;
            float mt = -3.0e38f;
#pragma unroll
            for (int a = 0; a < 8; a++) {
                int gj = j0 + jj0 + a;
                float s = (gj > gi + MEMLEN) ? -1.0e30f : S[rr][a] * scale;
                S[rr][a] = s;
                mt = fmaxf(mt, s);
            }
#pragma unroll
            for (int off = 8; off > 0; off >>= 1)
                mt = fmaxf(mt, __shfl_xor_sync(0xffffffffu, mt, off));
            float mn = fmaxf(mrow[rr], mt);
            float co = __expf(mrow[rr] - mn);
            mrow[rr] = mn;
            float rs = 0.f;
#pragma unroll
            for (int a = 0; a < 8; a++) {
                float p = __expf(S[rr][a] - mn);
                S[rr][a] = p;
                rs += p;
            }
#pragma unroll
            for (int off = 8; off > 0; off >>= 1)
                rs += __shfl_xor_sync(0xffffffffu, rs, off);
            lrow[rr] = lrow[rr] * co + rs;
#pragma unroll
            for (int c = 0; c < 4; c++) O[rr][c] *= co;
#pragma unroll
            for (int a = 0; a < 8; a++)
                Pt[(jj0 + a) * PT_LD + ii0 + rr] = S[rr][a];
        }
        __syncthreads();

        // --- PV: O[4 rows][4 d-cols] += P^T/V ---
#pragma unroll 8
        for (int jj = 0; jj < 128; jj++) {
            float4 p  = *(float4*)&Pt[jj * PT_LD + ii0];
            float4 vv = *(float4*)&Vs[jj * 64 + cgrp * 4];
            float pv[4]  = {p.x, p.y, p.z, p.w};
            float vvv[4] = {vv.x, vv.y, vv.z, vv.w};
#pragma unroll
            for (int rr = 0; rr < 4; rr++)
#pragma unroll
                for (int c = 0; c < 4; c++)
                    O[rr][c] = fmaf(pv[rr], vvv[c], O[rr][c]);
        }
    }

    // finalize: divide by l, write attn_vec [b, i, n*64+d]
#pragma unroll
    for (int rr = 0; rr < 4; rr++) {
        float inv = 1.f / lrow[rr];
        int gi = i0 + ii0 + rr;
        float4 o4 = make_float4(O[rr][0] * inv, O[rr][1] * inv,
                                O[rr][2] * inv, O[rr][3] * inv);
        *(float4*)(g_av + ((size_t)b * QLEN + gi) * (NH * DH) + n * DH + cgrp * 4) = o4;
    }
}

// ---------------------------------------------------------------------------
extern "C" void kernel_launch(void* const* d_in, const int* in_sizes, int n_in,
                              void* d_out, int out_size)
{
    const float* w   = (const float*)d_in[0];
    const float* r   = (const float*)d_in[1];
    const float* rwb = (const float*)d_in[2];
    const float* rrb = (const float*)d_in[3];
    const float* Wq  = (const float*)d_in[4];
    const float* Wkv = (const float*)d_in[5];
    const float* Wr  = (const float*)d_in[6];
    const float* Wo  = (const float*)d_in[7];
    // d_in[8] attn_mask, d_in[9] qlen: computed analytically (j <= i + MEMLEN)
    float* out = (float*)d_out;

    // Projections
    sgemm_k<0><<<dim3(DM / 128,     (BSZ * QLEN) / 128), 256>>>(w, Wq,  nullptr, DM,     DM);
    sgemm_k<1><<<dim3(2 * DM / 128, (BSZ * KLEN) / 128), 256>>>(w, Wkv, nullptr, 2 * DM, DM);
    sgemm_k<2><<<dim3(DM / 128,     KLEN / 128),         256>>>(r, Wr,  nullptr, DM,     DM);

    // Fused relative attention
    cudaFuncSetAttribute(attn_kernel, cudaFuncAttributeMaxDynamicSharedMemorySize,
                         ATTN_SMEM_BYTES);
    attn_kernel<<<BSZ * NH * (QLEN / BI), 256, ATTN_SMEM_BYTES>>>(rwb, rrb);

    // Output projection
    sgemm_k<3><<<dim3(DM / 128, (BSZ * QLEN) / 128), 256>>>(nullptr, Wo, out, DM, DM);
}

// round 5
// speedup vs baseline: 3.1629x; 3.1629x over previous
#include <cuda_runtime.h>
#include <cuda_bf16.h>
#include <cstdint>
#include <cstddef>

// ---------------------------------------------------------------------------
// Transformer-XL relative attention — all matmuls on tensor cores via
// mma.sync.m16n8k16 bf16 (hi/lo split, fp32 accum). tcgen05 is NOT available
// through this harness's PTX target (plain sm_103), so warp-level HMMA it is.
//
// rel_shift identity: for j <= i + 1024,
//   shift(BD)[b,i,j,n] = (q + r_r_bias) . rk[j - i + 1023, n, :]
// ---------------------------------------------------------------------------

constexpr int BSZ = 4, QLEN = 1024, KLEN = 2048, NH = 16, DH = 64, DM = 1024;

// ---- bf16 split global scratch --------------------------------------------
__device__ __nv_bfloat16 g_w_hi [(size_t)BSZ * KLEN * DM];
__device__ __nv_bfloat16 g_w_lo [(size_t)BSZ * KLEN * DM];
__device__ __nv_bfloat16 g_r_hi [(size_t)KLEN * DM];
__device__ __nv_bfloat16 g_r_lo [(size_t)KLEN * DM];
// transposed weights [N][K]
__device__ __nv_bfloat16 g_wqt_hi [(size_t)DM * DM],     g_wqt_lo [(size_t)DM * DM];
__device__ __nv_bfloat16 g_wkvt_hi[(size_t)2 * DM * DM], g_wkvt_lo[(size_t)2 * DM * DM];
__device__ __nv_bfloat16 g_wrt_hi [(size_t)DM * DM],     g_wrt_lo [(size_t)DM * DM];
__device__ __nv_bfloat16 g_wot_hi [(size_t)DM * DM],     g_wot_lo [(size_t)DM * DM];
// projection outputs, bf16 split. q with rwb / rrb biases folded in.
__device__ __nv_bfloat16 g_qw_hi[(size_t)BSZ * NH * QLEN * DH], g_qw_lo[(size_t)BSZ * NH * QLEN * DH];
__device__ __nv_bfloat16 g_qr_hi[(size_t)BSZ * NH * QLEN * DH], g_qr_lo[(size_t)BSZ * NH * QLEN * DH];
__device__ __nv_bfloat16 g_k_hi [(size_t)BSZ * NH * KLEN * DH], g_k_lo [(size_t)BSZ * NH * KLEN * DH];
__device__ __nv_bfloat16 g_v_hi [(size_t)BSZ * NH * KLEN * DH], g_v_lo [(size_t)BSZ * NH * KLEN * DH];
__device__ __nv_bfloat16 g_rk_hi[(size_t)NH * KLEN * DH],       g_rk_lo[(size_t)NH * KLEN * DH];
// attention output (input to Wo gemm)
__device__ __nv_bfloat16 g_av_hi[(size_t)BSZ * QLEN * DM], g_av_lo[(size_t)BSZ * QLEN * DM];

// ---------------------------------------------------------------------------
// helpers
// ---------------------------------------------------------------------------
__device__ __forceinline__ uint32_t smem_to_u32(const void* p) {
    uint32_t a;
    asm("{ .reg .u64 t; cvta.to.shared.u64 t, %1; cvt.u32.u64 %0, t; }"
        : "=r"(a) : "l"(p));
    return a;
}
__device__ __forceinline__ void ldsm4(uint32_t* r, uint32_t a) {
    asm volatile("ldmatrix.sync.aligned.m8n8.x4.shared.b16 {%0,%1,%2,%3}, [%4];"
                 : "=r"(r[0]), "=r"(r[1]), "=r"(r[2]), "=r"(r[3]) : "r"(a));
}
__device__ __forceinline__ void ldsm2(uint32_t* r, uint32_t a) {
    asm volatile("ldmatrix.sync.aligned.m8n8.x2.shared.b16 {%0,%1}, [%2];"
                 : "=r"(r[0]), "=r"(r[1]) : "r"(a));
}
__device__ __forceinline__ void ldsm2t(uint32_t* r, uint32_t a) {
    asm volatile("ldmatrix.sync.aligned.m8n8.x2.trans.shared.b16 {%0,%1}, [%2];"
                 : "=r"(r[0]), "=r"(r[1]) : "r"(a));
}
__device__ __forceinline__ void mma16816(float* d, const uint32_t* a, const uint32_t* b) {
    asm volatile("mma.sync.aligned.m16n8k16.row.col.f32.bf16.bf16.f32 "
                 "{%0,%1,%2,%3}, {%4,%5,%6,%7}, {%8,%9}, {%0,%1,%2,%3};"
                 : "+f"(d[0]), "+f"(d[1]), "+f"(d[2]), "+f"(d[3])
                 : "r"(a[0]), "r"(a[1]), "r"(a[2]), "r"(a[3]),
                   "r"(b[0]), "r"(b[1]));
}
#define CP16(sm, gm) \
    asm volatile("cp.async.cg.shared.global [%0], [%1], 16;" :: "r"(sm), "l"(gm))
#define CP_COMMIT() asm volatile("cp.async.commit_group;" ::: "memory")
#define CP_WAIT1()  asm volatile("cp.async.wait_group 1;" ::: "memory")
#define CP_WAIT0()  asm volatile("cp.async.wait_group 0;" ::: "memory")

__device__ __forceinline__ void store_split2(__nv_bfloat16* hi, __nv_bfloat16* lo,
                                             size_t off, float x, float y) {
    __nv_bfloat16 hx = __float2bfloat16(x), hy = __float2bfloat16(y);
    __nv_bfloat16 lx = __float2bfloat16(x - __bfloat162float(hx));
    __nv_bfloat16 ly = __float2bfloat16(y - __bfloat162float(hy));
    __nv_bfloat162 h2; h2.x = hx; h2.y = hy;
    __nv_bfloat162 l2; l2.x = lx; l2.y = ly;
    *(__nv_bfloat162*)(hi + off) = h2;
    *(__nv_bfloat162*)(lo + off) = l2;
}

// ---------------------------------------------------------------------------
// Pre-pass 1: fp32 -> bf16 hi/lo split (same layout). DST: 0=w, 1=r
// ---------------------------------------------------------------------------
template <int DST>
__global__ void convert_split(const float* __restrict__ src) {
    __nv_bfloat16* hi = (DST == 0) ? g_w_hi : g_r_hi;
    __nv_bfloat16* lo = (DST == 0) ? g_w_lo : g_r_lo;
    size_t i = ((size_t)blockIdx.x * blockDim.x + threadIdx.x) * 4;
    float4 v = *(const float4*)(src + i);
    float vv[4] = {v.x, v.y, v.z, v.w};
    __nv_bfloat16 h[4], l[4];
#pragma unroll
    for (int j = 0; j < 4; j++) {
        h[j] = __float2bfloat16(vv[j]);
        l[j] = __float2bfloat16(vv[j] - __bfloat162float(h[j]));
    }
    *(uint2*)(hi + i) = *(uint2*)h;
    *(uint2*)(lo + i) = *(uint2*)l;
}

// ---------------------------------------------------------------------------
// Pre-pass 2: W [K][N] fp32 -> Wt hi/lo [N][K] bf16. DST: 0=Wq,1=Wkv,2=Wr,3=Wo
// ---------------------------------------------------------------------------
template <int DST>
__global__ void transpose_split(const float* __restrict__ W, int N) {
    __shared__ float t[32][33];
    __nv_bfloat16* hi = (DST == 0) ? g_wqt_hi : (DST == 1) ? g_wkvt_hi
                       : (DST == 2) ? g_wrt_hi : g_wot_hi;
    __nv_bfloat16* lo = (DST == 0) ? g_wqt_lo : (DST == 1) ? g_wkvt_lo
                       : (DST == 2) ? g_wrt_lo : g_wot_lo;
    int n0 = blockIdx.x * 32, k0 = blockIdx.y * 32;
    int tx = threadIdx.x, ty = threadIdx.y;
#pragma unroll
    for (int i = 0; i < 4; i++)
        t[ty + 8 * i][tx] = W[(size_t)(k0 + ty + 8 * i) * N + n0 + tx];
    __syncthreads();
#pragma unroll
    for (int i = 0; i < 4; i++) {
        float v = t[tx][ty + 8 * i];
        __nv_bfloat16 h = __float2bfloat16(v);
        __nv_bfloat16 l = __float2bfloat16(v - __bfloat162float(h));
        size_t o = (size_t)(n0 + ty + 8 * i) * DM + k0 + tx;
        hi[o] = h;
        lo[o] = l;
    }
}

// ---------------------------------------------------------------------------
// HMMA split-bf16 GEMM: C[M,N] = A[M,K=1024] * Bt[N,K]^T
// 128x128 tile, 8 warps (warp tile 32x64), cp.async double-buffered chunks of 64.
// MODE epilogues: 0 -> Qw/Qr(+bias) split, 1 -> K/V split, 2 -> rk split,
//                 3 -> fp32 C (d_out), A = g_av split.
// ---------------------------------------------------------------------------
constexpr int GEMM_BUF = 73728;          // 4 arrays * 128 rows * 144B
constexpr int GEMM_SMEM = 2 * GEMM_BUF;  // 147456

template <int MODE>
__global__ void __launch_bounds__(256, 1)
hgemm(const float* __restrict__ rwb, const float* __restrict__ rrb,
      float* __restrict__ C)
{
    extern __shared__ char smc[];
    const uint32_t sb = smem_to_u32(smc);
    const int tid = threadIdx.x, lane = tid & 31, wid = tid >> 5;
    const int wm = wid >> 1, wn = wid & 1;
    const int m0 = blockIdx.y * 128, n0 = blockIdx.x * 128;

    const __nv_bfloat16 *Ah, *Al, *Bh, *Bl;
    if (MODE == 0)      { Ah = g_w_hi;  Al = g_w_lo;  Bh = g_wqt_hi;  Bl = g_wqt_lo;  }
    else if (MODE == 1) { Ah = g_w_hi;  Al = g_w_lo;  Bh = g_wkvt_hi; Bl = g_wkvt_lo; }
    else if (MODE == 2) { Ah = g_r_hi;  Al = g_r_lo;  Bh = g_wrt_hi;  Bl = g_wrt_lo;  }
    else                { Ah = g_av_hi; Al = g_av_lo; Bh = g_wot_hi;  Bl = g_wot_lo;  }

    float acc[2][8][4];
#pragma unroll
    for (int a = 0; a < 2; a++)
#pragma unroll
        for (int b = 0; b < 8; b++)
#pragma unroll
            for (int c = 0; c < 4; c++) acc[a][b][c] = 0.f;

    auto load_chunk = [&](int c, int buf) {
        const int k0 = c * 64;
        const uint32_t s0 = sb + buf * GEMM_BUF;
#pragma unroll
        for (int it = 0; it < 4; it++) {
            int u = tid + it * 256;
            int row = u >> 3, kk = (u & 7) * 8;
            uint32_t so = row * 144 + kk * 2;
            int am = m0 + row;
            int grow = (MODE == 0) ? (((am >> 10) << 11) + QLEN + (am & (QLEN - 1))) : am;
            size_t ao = (size_t)grow * DM + k0 + kk;
            size_t bo = (size_t)(n0 + row) * DM + k0 + kk;
            CP16(s0 + so,         Ah + ao);
            CP16(s0 + 18432 + so, Al + ao);
            CP16(s0 + 36864 + so, Bh + bo);
            CP16(s0 + 55296 + so, Bl + bo);
        }
        CP_COMMIT();
    };

    load_chunk(0, 0);
#pragma unroll 1
    for (int c = 0; c < 16; c++) {
        if (c + 1 < 16) { load_chunk(c + 1, (c + 1) & 1); CP_WAIT1(); }
        else            { CP_WAIT0(); }
        __syncthreads();
        const uint32_t s0 = sb + (c & 1) * GEMM_BUF;
        const uint32_t aBase = s0 + (wm * 32 + (lane & 15)) * 144 + ((lane >> 4) * 8) * 2;
        const uint32_t bBase = s0 + 36864 + (wn * 64 + (lane & 7)) * 144
                             + (((lane >> 3) & 1) * 8) * 2;
#pragma unroll
        for (int kk = 0; kk < 4; kk++) {
            uint32_t ah[2][4], al[2][4];
#pragma unroll
            for (int ms = 0; ms < 2; ms++) {
                uint32_t aa = aBase + ms * 16 * 144 + kk * 32;
                ldsm4(ah[ms], aa);
                ldsm4(al[ms], aa + 18432);
            }
#pragma unroll
            for (int ns = 0; ns < 8; ns++) {
                uint32_t ba = bBase + ns * 8 * 144 + kk * 32;
                uint32_t bh2[2], bl2[2];
                ldsm2(bh2, ba);
                ldsm2(bl2, ba + 18432);
#pragma unroll
                for (int ms = 0; ms < 2; ms++) {
                    mma16816(acc[ms][ns], ah[ms], bh2);
                    mma16816(acc[ms][ns], ah[ms], bl2);
                    mma16816(acc[ms][ns], al[ms], bh2);
                }
            }
        }
        __syncthreads();
    }

    // epilogue
#pragma unroll
    for (int ms = 0; ms < 2; ms++) {
        int r0 = m0 + wm * 32 + ms * 16 + (lane >> 2);
#pragma unroll
        for (int ns = 0; ns < 8; ns++) {
            int col = n0 + wn * 64 + ns * 8 + (lane & 3) * 2;
#pragma unroll
            for (int h = 0; h < 2; h++) {
                int row = r0 + h * 8;
                float x = acc[ms][ns][h * 2 + 0];
                float y = acc[ms][ns][h * 2 + 1];
                if (MODE == 0) {
                    int bb = row >> 10, ii = row & 1023;
                    int head = col >> 6, d = col & 63;
                    size_t off = (((size_t)(bb * NH + head)) * QLEN + ii) * DH + d;
                    store_split2(g_qw_hi, g_qw_lo, off, x + rwb[col], y + rwb[col + 1]);
                    store_split2(g_qr_hi, g_qr_lo, off, x + rrb[col], y + rrb[col + 1]);
                } else if (MODE == 1) {
                    int bb = row >> 11, jj = row & 2047;
                    int cc = (col < DM) ? col : col - DM;
                    int head = cc >> 6, d = cc & 63;
                    size_t off = (((size_t)(bb * NH + head)) * KLEN + jj) * DH + d;
                    if (col < DM) store_split2(g_k_hi, g_k_lo, off, x, y);
                    else          store_split2(g_v_hi, g_v_lo, off, x, y);
                } else if (MODE == 2) {
                    int head = col >> 6, d = col & 63;
                    size_t off = ((size_t)head * KLEN + row) * DH + d;
                    store_split2(g_rk_hi, g_rk_lo, off, x, y);
                } else {
                    *(float2*)(C + (size_t)row * DM + col) = make_float2(x, y);
                }
            }
        }
    }
}

// ---------------------------------------------------------------------------
// HMMA flash attention with relative shift.
// CTA: (bh, 64-query itile), 256 threads, 8 warps (wm in [0,4) x wn in [0,2)).
// Per 64-key tile: S = Qw@K^T, T = Qr@Rw^T (128-wide window GEMM),
// softmax gathers T[ii][jj-ii+63], P split to bf16, O += P@V (ldmatrix.trans).
// ---------------------------------------------------------------------------
constexpr int sQWH = 0, sQWL = 9216, sQRH = 18432, sQRL = 27648;   // 64x72 bf16 each
constexpr int sKH = 36864, sKL = 46080, sVH = 55296, sVL = 64512;  // 64x72 bf16 each
constexpr int sRWH = 73728, sRWL = 92160;                           // 128x72 bf16 each
constexpr int sS = 110592;            // 64 x 68 f32
constexpr int sT = 128000;            // 64 x 132 f32
constexpr int sPH = 161792, sPL = 171008;  // 64x72 bf16 each
constexpr int sCO = 180224, sLS = 180480;
constexpr int ATTN_SMEM = 180736;

__global__ void __launch_bounds__(256, 1) attn2()
{
    extern __shared__ char smc[];
    const uint32_t sb = smem_to_u32(smc);
    const int tid = threadIdx.x, lane = tid & 31, wid = tid >> 5;
    const int wm = wid >> 1, wn = wid & 1;
    const int itile = blockIdx.x & 15, bh = blockIdx.x >> 4;
    const int head = bh & 15, bb = bh >> 4;
    const int i0 = itile * 64;

    // load Q tiles (both biased variants, hi/lo)
#pragma unroll
    for (int it = 0; it < 2; it++) {
        int u = tid + it * 256;
        int row = u >> 3, kk = (u & 7) * 8;
        uint32_t so = row * 144 + kk * 2;
        size_t off = ((size_t)bh * QLEN + i0 + row) * DH + kk;
        *(uint4*)(smc + sQWH + so) = *(const uint4*)(g_qw_hi + off);
        *(uint4*)(smc + sQWL + so) = *(const uint4*)(g_qw_lo + off);
        *(uint4*)(smc + sQRH + so) = *(const uint4*)(g_qr_hi + off);
        *(uint4*)(smc + sQRL + so) = *(const uint4*)(g_qr_lo + off);
    }
    __syncthreads();

    // cache Q fragments in registers (rows wm*16..+15, all 4 k-steps)
    uint32_t qwh[4][4], qwl[4][4], qrh[4][4], qrl[4][4];
    {
        uint32_t ab = sb + sQWH + (wm * 16 + (lane & 15)) * 144 + ((lane >> 4) * 8) * 2;
#pragma unroll
        for (int kk = 0; kk < 4; kk++) {
            ldsm4(qwh[kk], ab + kk * 32);
            ldsm4(qwl[kk], ab + 9216 + kk * 32);
            ldsm4(qrh[kk], ab + 18432 + kk * 32);
            ldsm4(qrl[kk], ab + 27648 + kk * 32);
        }
    }

    float o[4][4];
#pragma unroll
    for (int a = 0; a < 4; a++)
#pragma unroll
        for (int b = 0; b < 4; b++) o[a][b] = 0.f;
    float mrow = -3.0e38f, lrow = 0.f;
    const int srow = tid >> 2, sc0 = (tid & 3) * 16;
    const int ntiles = itile + 17;

#pragma unroll 1
    for (int t = 0; t < ntiles; t++) {
        const int j0 = t * 64;
        __syncthreads();

        // K / V tiles
#pragma unroll
        for (int it = 0; it < 2; it++) {
            int u = tid + it * 256;
            int row = u >> 3, kk = (u & 7) * 8;
            uint32_t so = row * 144 + kk * 2;
            size_t off = ((size_t)bh * KLEN + j0 + row) * DH + kk;
            *(uint4*)(smc + sKH + so) = *(const uint4*)(g_k_hi + off);
            *(uint4*)(smc + sKL + so) = *(const uint4*)(g_k_lo + off);
            *(uint4*)(smc + sVH + so) = *(const uint4*)(g_v_hi + off);
            *(uint4*)(smc + sVL + so) = *(const uint4*)(g_v_lo + off);
        }
        // Rw window: local row r <-> d_rel = dbase + r; d_rel = j - i + 1023
        const int dbase = j0 - i0 + 960;
#pragma unroll
        for (int it = 0; it < 4; it++) {
            int u = tid + it * 256;
            int row = u >> 3, kk = (u & 7) * 8;
            int dr = dbase + row;
            dr = dr < 0 ? 0 : (dr > KLEN - 1 ? KLEN - 1 : dr); // OOB rows masked anyway
            uint32_t so = row * 144 + kk * 2;
            size_t off = ((size_t)head * KLEN + dr) * DH + kk;
            *(uint4*)(smc + sRWH + so) = *(const uint4*)(g_rk_hi + off);
            *(uint4*)(smc + sRWL + so) = *(const uint4*)(g_rk_lo + off);
        }
        __syncthreads();

        // ---- phase 1: S (16x32 per warp) and T (16x64 per warp) ----
        float sacc[4][4], tacc[8][4];
#pragma unroll
        for (int a = 0; a < 4; a++)
#pragma unroll
            for (int b = 0; b < 4; b++) sacc[a][b] = 0.f;
#pragma unroll
        for (int a = 0; a < 8; a++)
#pragma unroll
            for (int b = 0; b < 4; b++) tacc[a][b] = 0.f;
        {
            const uint32_t kb = sb + sKH + (lane & 7) * 144 + (((lane >> 3) & 1) * 8) * 2;
            const uint32_t rb = sb + sRWH + (lane & 7) * 144 + (((lane >> 3) & 1) * 8) * 2;
#pragma unroll
            for (int kk = 0; kk < 4; kk++) {
#pragma unroll
                for (int ns = 0; ns < 4; ns++) {
                    uint32_t ba = kb + (wn * 32 + ns * 8) * 144 + kk * 32;
                    uint32_t bh2[2], bl2[2];
                    ldsm2(bh2, ba);
                    ldsm2(bl2, ba + 9216);
                    mma16816(sacc[ns], qwh[kk], bh2);
                    mma16816(sacc[ns], qwh[kk], bl2);
                    mma16816(sacc[ns], qwl[kk], bh2);
                }
#pragma unroll
                for (int ns = 0; ns < 8; ns++) {
                    uint32_t ba = rb + (wn * 64 + ns * 8) * 144 + kk * 32;
                    uint32_t bh2[2], bl2[2];
                    ldsm2(bh2, ba);
                    ldsm2(bl2, ba + 18432);
                    mma16816(tacc[ns], qrh[kk], bh2);
                    mma16816(tacc[ns], qrh[kk], bl2);
                    mma16816(tacc[ns], qrl[kk], bh2);
                }
            }
        }
        {
            int r0 = wm * 16 + (lane >> 2);
            float* Sf = (float*)(smc + sS);
            float* Tf = (float*)(smc + sT);
#pragma unroll
            for (int ns = 0; ns < 4; ns++) {
                int c = wn * 32 + ns * 8 + (lane & 3) * 2;
                *(float2*)&Sf[r0 * 68 + c]       = make_float2(sacc[ns][0], sacc[ns][1]);
                *(float2*)&Sf[(r0 + 8) * 68 + c] = make_float2(sacc[ns][2], sacc[ns][3]);
            }
#pragma unroll
            for (int ns = 0; ns < 8; ns++) {
                int c = wn * 64 + ns * 8 + (lane & 3) * 2;
                *(float2*)&Tf[r0 * 132 + c]       = make_float2(tacc[ns][0], tacc[ns][1]);
                *(float2*)&Tf[(r0 + 8) * 132 + c] = make_float2(tacc[ns][2], tacc[ns][3]);
            }
        }
        __syncthreads();

        // ---- softmax (4 threads per row, 16 cols each) ----
        {
            const float* Sf = (const float*)(smc + sS);
            const float* Tf = (const float*)(smc + sT);
            const int gi = i0 + srow;
            float sv[16];
            float mt = -3.0e38f;
#pragma unroll
            for (int c2 = 0; c2 < 16; c2++) {
                int c = sc0 + c2;
                float s = (Sf[srow * 68 + c] + Tf[srow * 132 + (c - srow + 63)]) * 0.125f;
                s = ((j0 + c) > gi + 1024) ? -1.0e30f : s;
                sv[c2] = s;
                mt = fmaxf(mt, s);
            }
            mt = fmaxf(mt, __shfl_xor_sync(0xffffffffu, mt, 1));
            mt = fmaxf(mt, __shfl_xor_sync(0xffffffffu, mt, 2));
            float mn = fmaxf(mrow, mt);
            float co = __expf(mrow - mn);
            mrow = mn;
            float rs = 0.f;
            __nv_bfloat16* Ph = (__nv_bfloat16*)(smc + sPH);
            __nv_bfloat16* Pl = (__nv_bfloat16*)(smc + sPL);
#pragma unroll
            for (int c2 = 0; c2 < 16; c2 += 2) {
                float p0 = __expf(sv[c2] - mn);
                float p1 = __expf(sv[c2 + 1] - mn);
                rs += p0 + p1;
                __nv_bfloat16 h0 = __float2bfloat16(p0), h1 = __float2bfloat16(p1);
                __nv_bfloat162 h2; h2.x = h0; h2.y = h1;
                __nv_bfloat162 l2;
                l2.x = __float2bfloat16(p0 - __bfloat162float(h0));
                l2.y = __float2bfloat16(p1 - __bfloat162float(h1));
                int c = sc0 + c2;
                *(__nv_bfloat162*)&Ph[srow * 72 + c] = h2;
                *(__nv_bfloat162*)&Pl[srow * 72 + c] = l2;
            }
            rs += __shfl_xor_sync(0xffffffffu, rs, 1);
            rs += __shfl_xor_sync(0xffffffffu, rs, 2);
            lrow = lrow * co + rs;
            if ((tid & 3) == 0) ((float*)(smc + sCO))[srow] = co;
        }
        __syncthreads();

        // ---- PV: O (16x32 per warp) = O*co + P @ V ----
        {
            float co0 = ((float*)(smc + sCO))[wm * 16 + (lane >> 2)];
            float co1 = ((float*)(smc + sCO))[wm * 16 + (lane >> 2) + 8];
#pragma unroll
            for (int ns = 0; ns < 4; ns++) {
                o[ns][0] *= co0; o[ns][1] *= co0;
                o[ns][2] *= co1; o[ns][3] *= co1;
            }
            const uint32_t pb = sb + sPH + (wm * 16 + (lane & 15)) * 144
                              + ((lane >> 4) * 8) * 2;
            const uint32_t vb = sb + sVH + (lane & 15) * 144 + (wn * 32) * 2;
#pragma unroll
            for (int kk = 0; kk < 4; kk++) {
                uint32_t pah[4], pal[4];
                ldsm4(pah, pb + kk * 32);
                ldsm4(pal, pb + 9216 + kk * 32);
#pragma unroll
                for (int ns = 0; ns < 4; ns++) {
                    uint32_t va = vb + kk * 16 * 144 + ns * 8 * 2;
                    uint32_t vh2[2], vl2[2];
                    ldsm2t(vh2, va);
                    ldsm2t(vl2, va + 9216);
                    mma16816(o[ns], pah, vh2);
                    mma16816(o[ns], pah, vl2);
                    mma16816(o[ns], pal, vh2);
                }
            }
        }
    }

    // ---- finalize: O / l, split to bf16, write [b, i, head*64+d] ----
    if ((tid & 3) == 0) ((float*)(smc + sLS))[srow] = lrow;
    __syncthreads();
    {
        float li0 = 1.f / ((float*)(smc + sLS))[wm * 16 + (lane >> 2)];
        float li1 = 1.f / ((float*)(smc + sLS))[wm * 16 + (lane >> 2) + 8];
        int gi0 = i0 + wm * 16 + (lane >> 2);
#pragma unroll
        for (int ns = 0; ns < 4; ns++) {
            int d = wn * 32 + ns * 8 + (lane & 3) * 2;
            size_t off0 = ((size_t)bb * QLEN + gi0) * DM + head * DH + d;
            store_split2(g_av_hi, g_av_lo, off0, o[ns][0] * li0, o[ns][1] * li0);
            store_split2(g_av_hi, g_av_lo, off0 + 8 * DM, o[ns][2] * li1, o[ns][3] * li1);
        }
    }
}

// ---------------------------------------------------------------------------
extern "C" void kernel_launch(void* const* d_in, const int* in_sizes, int n_in,
                              void* d_out, int out_size)
{
    const float* w   = (const float*)d_in[0];
    const float* r   = (const float*)d_in[1];
    const float* rwb = (const float*)d_in[2];
    const float* rrb = (const float*)d_in[3];
    const float* Wq  = (const float*)d_in[4];
    const float* Wkv = (const float*)d_in[5];
    const float* Wr  = (const float*)d_in[6];
    const float* Wo  = (const float*)d_in[7];
    float* out = (float*)d_out;

    // pre-pass: split inputs, transpose+split weights
    convert_split<0><<<(BSZ * KLEN * DM) / 1024, 256>>>(w);
    convert_split<1><<<(KLEN * DM) / 1024, 256>>>(r);
    transpose_split<0><<<dim3(DM / 32, DM / 32), dim3(32, 8)>>>(Wq, DM);
    transpose_split<1><<<dim3(2 * DM / 32, DM / 32), dim3(32, 8)>>>(Wkv, 2 * DM);
    transpose_split<2><<<dim3(DM / 32, DM / 32), dim3(32, 8)>>>(Wr, DM);
    transpose_split<3><<<dim3(DM / 32, DM / 32), dim3(32, 8)>>>(Wo, DM);

    cudaFuncSetAttribute(hgemm<0>, cudaFuncAttributeMaxDynamicSharedMemorySize, GEMM_SMEM);
    cudaFuncSetAttribute(hgemm<1>, cudaFuncAttributeMaxDynamicSharedMemorySize, GEMM_SMEM);
    cudaFuncSetAttribute(hgemm<2>, cudaFuncAttributeMaxDynamicSharedMemorySize, GEMM_SMEM);
    cudaFuncSetAttribute(hgemm<3>, cudaFuncAttributeMaxDynamicSharedMemorySize, GEMM_SMEM);
    cudaFuncSetAttribute(attn2, cudaFuncAttributeMaxDynamicSharedMemorySize, ATTN_SMEM);

    // projections
    hgemm<0><<<dim3(DM / 128,     (BSZ * QLEN) / 128), 256, GEMM_SMEM>>>(rwb, rrb, nullptr);
    hgemm<1><<<dim3(2 * DM / 128, (BSZ * KLEN) / 128), 256, GEMM_SMEM>>>(nullptr, nullptr, nullptr);
    hgemm<2><<<dim3(DM / 128,     KLEN / 128),         256, GEMM_SMEM>>>(nullptr, nullptr, nullptr);

    // fused relative attention
    attn2<<<BSZ * NH * (QLEN / 64), 256, ATTN_SMEM>>>();

    // output projection
    hgemm<3><<<dim3(DM / 128, (BSZ * QLEN) / 128), 256, GEMM_SMEM>>>(nullptr, nullptr, out);
}

// round 6
// speedup vs baseline: 3.2865x; 1.0391x over previous
#include <cuda_runtime.h>
#include <cuda_bf16.h>
#include <cstdint>
#include <cstddef>

// ---------------------------------------------------------------------------
// Transformer-XL relative attention — all matmuls via mma.sync m16n8k16 bf16
// (hi/lo split, fp32 accum). tcgen05 unavailable (harness targets plain sm_103).
//
// rel_shift identity: for j <= i + 1024,
//   shift(BD)[b,i,j,n] = (q + r_r_bias) . rk[j - i + 1023, n, :]
// ---------------------------------------------------------------------------

constexpr int BSZ = 4, QLEN = 1024, KLEN = 2048, NH = 16, DH = 64, DM = 1024;

// ---- bf16 split global scratch --------------------------------------------
__device__ __nv_bfloat16 g_w_hi [(size_t)BSZ * KLEN * DM];
__device__ __nv_bfloat16 g_w_lo [(size_t)BSZ * KLEN * DM];
__device__ __nv_bfloat16 g_r_hi [(size_t)KLEN * DM];
__device__ __nv_bfloat16 g_r_lo [(size_t)KLEN * DM];
__device__ __nv_bfloat16 g_wqt_hi [(size_t)DM * DM],     g_wqt_lo [(size_t)DM * DM];
__device__ __nv_bfloat16 g_wkvt_hi[(size_t)2 * DM * DM], g_wkvt_lo[(size_t)2 * DM * DM];
__device__ __nv_bfloat16 g_wrt_hi [(size_t)DM * DM],     g_wrt_lo [(size_t)DM * DM];
__device__ __nv_bfloat16 g_wot_hi [(size_t)DM * DM],     g_wot_lo [(size_t)DM * DM];
__device__ __nv_bfloat16 g_qw_hi[(size_t)BSZ * NH * QLEN * DH], g_qw_lo[(size_t)BSZ * NH * QLEN * DH];
__device__ __nv_bfloat16 g_qr_hi[(size_t)BSZ * NH * QLEN * DH], g_qr_lo[(size_t)BSZ * NH * QLEN * DH];
__device__ __nv_bfloat16 g_k_hi [(size_t)BSZ * NH * KLEN * DH], g_k_lo [(size_t)BSZ * NH * KLEN * DH];
__device__ __nv_bfloat16 g_v_hi [(size_t)BSZ * NH * KLEN * DH], g_v_lo [(size_t)BSZ * NH * KLEN * DH];
__device__ __nv_bfloat16 g_rk_hi[(size_t)NH * KLEN * DH],       g_rk_lo[(size_t)NH * KLEN * DH];
__device__ __nv_bfloat16 g_av_hi[(size_t)BSZ * QLEN * DM], g_av_lo[(size_t)BSZ * QLEN * DM];

// ---------------------------------------------------------------------------
// helpers
// ---------------------------------------------------------------------------
__device__ __forceinline__ uint32_t smem_to_u32(const void* p) {
    uint32_t a;
    asm("{ .reg .u64 t; cvta.to.shared.u64 t, %1; cvt.u32.u64 %0, t; }"
        : "=r"(a) : "l"(p));
    return a;
}
__device__ __forceinline__ void ldsm4(uint32_t* r, uint32_t a) {
    asm volatile("ldmatrix.sync.aligned.m8n8.x4.shared.b16 {%0,%1,%2,%3}, [%4];"
                 : "=r"(r[0]), "=r"(r[1]), "=r"(r[2]), "=r"(r[3]) : "r"(a));
}
__device__ __forceinline__ void ldsm2(uint32_t* r, uint32_t a) {
    asm volatile("ldmatrix.sync.aligned.m8n8.x2.shared.b16 {%0,%1}, [%2];"
                 : "=r"(r[0]), "=r"(r[1]) : "r"(a));
}
__device__ __forceinline__ void ldsm2t(uint32_t* r, uint32_t a) {
    asm volatile("ldmatrix.sync.aligned.m8n8.x2.trans.shared.b16 {%0,%1}, [%2];"
                 : "=r"(r[0]), "=r"(r[1]) : "r"(a));
}
__device__ __forceinline__ void mma16816(float* d, const uint32_t* a, const uint32_t* b) {
    asm volatile("mma.sync.aligned.m16n8k16.row.col.f32.bf16.bf16.f32 "
                 "{%0,%1,%2,%3}, {%4,%5,%6,%7}, {%8,%9}, {%0,%1,%2,%3};"
                 : "+f"(d[0]), "+f"(d[1]), "+f"(d[2]), "+f"(d[3])
                 : "r"(a[0]), "r"(a[1]), "r"(a[2]), "r"(a[3]),
                   "r"(b[0]), "r"(b[1]));
}
#define CP16(sm, gm) \
    asm volatile("cp.async.cg.shared.global [%0], [%1], 16;" :: "r"(sm), "l"(gm))
#define CP_COMMIT() asm volatile("cp.async.commit_group;" ::: "memory")
#define CP_WAIT1()  asm volatile("cp.async.wait_group 1;" ::: "memory")
#define CP_WAIT0()  asm volatile("cp.async.wait_group 0;" ::: "memory")

__device__ __forceinline__ void store_split2(__nv_bfloat16* hi, __nv_bfloat16* lo,
                                             size_t off, float x, float y) {
    __nv_bfloat16 hx = __float2bfloat16(x), hy = __float2bfloat16(y);
    __nv_bfloat16 lx = __float2bfloat16(x - __bfloat162float(hx));
    __nv_bfloat16 ly = __float2bfloat16(y - __bfloat162float(hy));
    __nv_bfloat162 h2; h2.x = hx; h2.y = hy;
    __nv_bfloat162 l2; l2.x = lx; l2.y = ly;
    *(__nv_bfloat162*)(hi + off) = h2;
    *(__nv_bfloat162*)(lo + off) = l2;
}

// ---------------------------------------------------------------------------
// Pre-pass 1: fp32 -> bf16 hi/lo split (same layout). DST: 0=w, 1=r
// ---------------------------------------------------------------------------
template <int DST>
__global__ void convert_split(const float* __restrict__ src) {
    __nv_bfloat16* hi = (DST == 0) ? g_w_hi : g_r_hi;
    __nv_bfloat16* lo = (DST == 0) ? g_w_lo : g_r_lo;
    size_t i = ((size_t)blockIdx.x * blockDim.x + threadIdx.x) * 4;
    float4 v = *(const float4*)(src + i);
    float vv[4] = {v.x, v.y, v.z, v.w};
    __nv_bfloat16 h[4], l[4];
#pragma unroll
    for (int j = 0; j < 4; j++) {
        h[j] = __float2bfloat16(vv[j]);
        l[j] = __float2bfloat16(vv[j] - __bfloat162float(h[j]));
    }
    *(uint2*)(hi + i) = *(uint2*)h;
    *(uint2*)(lo + i) = *(uint2*)l;
}

// ---------------------------------------------------------------------------
// Pre-pass 2: W [K][N] fp32 -> Wt hi/lo [N][K] bf16. DST: 0=Wq,1=Wkv,2=Wr,3=Wo
// ---------------------------------------------------------------------------
template <int DST>
__global__ void transpose_split(const float* __restrict__ W, int N) {
    __shared__ float t[32][33];
    __nv_bfloat16* hi = (DST == 0) ? g_wqt_hi : (DST == 1) ? g_wkvt_hi
                       : (DST == 2) ? g_wrt_hi : g_wot_hi;
    __nv_bfloat16* lo = (DST == 0) ? g_wqt_lo : (DST == 1) ? g_wkvt_lo
                       : (DST == 2) ? g_wrt_lo : g_wot_lo;
    int n0 = blockIdx.x * 32, k0 = blockIdx.y * 32;
    int tx = threadIdx.x, ty = threadIdx.y;
#pragma unroll
    for (int i = 0; i < 4; i++)
        t[ty + 8 * i][tx] = W[(size_t)(k0 + ty + 8 * i) * N + n0 + tx];
    __syncthreads();
#pragma unroll
    for (int i = 0; i < 4; i++) {
        float v = t[tx][ty + 8 * i];
        __nv_bfloat16 h = __float2bfloat16(v);
        __nv_bfloat16 l = __float2bfloat16(v - __bfloat162float(h));
        size_t o = (size_t)(n0 + ty + 8 * i) * DM + k0 + tx;
        hi[o] = h;
        lo[o] = l;
    }
}

// ---------------------------------------------------------------------------
// HMMA split-bf16 GEMM body. 128x128 tile, 8 warps (32x64 warp tile),
// cp.async double-buffered chunks of 64 along K=1024.
// mode: 0 -> Qw/Qr(+bias), 1 -> K/V, 2 -> rk, 3 -> fp32 C (d_out)
// ---------------------------------------------------------------------------
constexpr int GEMM_BUF = 73728;          // 4 arrays * 128 rows * 144B
constexpr int GEMM_SMEM = 2 * GEMM_BUF;  // 147456

__device__ __forceinline__ void hgemm_body(
    int mode, int m0, int n0,
    const __nv_bfloat16* __restrict__ Ah, const __nv_bfloat16* __restrict__ Al,
    const __nv_bfloat16* __restrict__ Bh, const __nv_bfloat16* __restrict__ Bl,
    const float* __restrict__ rwb, const float* __restrict__ rrb,
    float* __restrict__ C, char* smc)
{
    const uint32_t sb = smem_to_u32(smc);
    const int tid = threadIdx.x, lane = tid & 31, wid = tid >> 5;
    const int wm = wid >> 1, wn = wid & 1;

    float acc[2][8][4];
#pragma unroll
    for (int a = 0; a < 2; a++)
#pragma unroll
        for (int b = 0; b < 8; b++)
#pragma unroll
            for (int c = 0; c < 4; c++) acc[a][b][c] = 0.f;

    auto load_chunk = [&](int c, int buf) {
        const int k0 = c * 64;
        const uint32_t s0 = sb + buf * GEMM_BUF;
#pragma unroll
        for (int it = 0; it < 4; it++) {
            int u = tid + it * 256;
            int row = u >> 3, kk = (u & 7) * 8;
            uint32_t so = row * 144 + kk * 2;
            int am = m0 + row;
            int grow = (mode == 0) ? (((am >> 10) << 11) + QLEN + (am & (QLEN - 1))) : am;
            size_t ao = (size_t)grow * DM + k0 + kk;
            size_t bo = (size_t)(n0 + row) * DM + k0 + kk;
            CP16(s0 + so,         Ah + ao);
            CP16(s0 + 18432 + so, Al + ao);
            CP16(s0 + 36864 + so, Bh + bo);
            CP16(s0 + 55296 + so, Bl + bo);
        }
        CP_COMMIT();
    };

    load_chunk(0, 0);
#pragma unroll 1
    for (int c = 0; c < 16; c++) {
        if (c + 1 < 16) { load_chunk(c + 1, (c + 1) & 1); CP_WAIT1(); }
        else            { CP_WAIT0(); }
        __syncthreads();
        const uint32_t s0 = sb + (c & 1) * GEMM_BUF;
        const uint32_t aBase = s0 + (wm * 32 + (lane & 15)) * 144 + ((lane >> 4) * 8) * 2;
        const uint32_t bBase = s0 + 36864 + (wn * 64 + (lane & 7)) * 144
                             + (((lane >> 3) & 1) * 8) * 2;
#pragma unroll
        for (int kk = 0; kk < 4; kk++) {
            uint32_t ah[2][4], al[2][4];
#pragma unroll
            for (int ms = 0; ms < 2; ms++) {
                uint32_t aa = aBase + ms * 16 * 144 + kk * 32;
                ldsm4(ah[ms], aa);
                ldsm4(al[ms], aa + 18432);
            }
#pragma unroll
            for (int ns = 0; ns < 8; ns++) {
                uint32_t ba = bBase + ns * 8 * 144 + kk * 32;
                uint32_t bh2[2], bl2[2];
                ldsm2(bh2, ba);
                ldsm2(bl2, ba + 18432);
#pragma unroll
                for (int ms = 0; ms < 2; ms++) {
                    mma16816(acc[ms][ns], ah[ms], bh2);
                    mma16816(acc[ms][ns], ah[ms], bl2);
                    mma16816(acc[ms][ns], al[ms], bh2);
                }
            }
        }
        __syncthreads();
    }

    // epilogue
#pragma unroll
    for (int ms = 0; ms < 2; ms++) {
        int r0 = m0 + wm * 32 + ms * 16 + (lane >> 2);
#pragma unroll
        for (int ns = 0; ns < 8; ns++) {
            int col = n0 + wn * 64 + ns * 8 + (lane & 3) * 2;
#pragma unroll
            for (int h = 0; h < 2; h++) {
                int row = r0 + h * 8;
                float x = acc[ms][ns][h * 2 + 0];
                float y = acc[ms][ns][h * 2 + 1];
                if (mode == 0) {
                    int bb = row >> 10, ii = row & 1023;
                    int head = col >> 6, d = col & 63;
                    size_t off = (((size_t)(bb * NH + head)) * QLEN + ii) * DH + d;
                    store_split2(g_qw_hi, g_qw_lo, off, x + rwb[col], y + rwb[col + 1]);
                    store_split2(g_qr_hi, g_qr_lo, off, x + rrb[col], y + rrb[col + 1]);
                } else if (mode == 1) {
                    int bb = row >> 11, jj = row & 2047;
                    int cc = (col < DM) ? col : col - DM;
                    int head = cc >> 6, d = cc & 63;
                    size_t off = (((size_t)(bb * NH + head)) * KLEN + jj) * DH + d;
                    if (col < DM) store_split2(g_k_hi, g_k_lo, off, x, y);
                    else          store_split2(g_v_hi, g_v_lo, off, x, y);
                } else if (mode == 2) {
                    int head = col >> 6, d = col & 63;
                    size_t off = ((size_t)head * KLEN + row) * DH + d;
                    store_split2(g_rk_hi, g_rk_lo, off, x, y);
                } else {
                    *(float2*)(C + (size_t)row * DM + col) = make_float2(x, y);
                }
            }
        }
    }
}

// merged Q / KV / R projections: one launch, blockIdx-decoded mode
__global__ void __launch_bounds__(256, 1)
hgemm_proj(const float* __restrict__ rwb, const float* __restrict__ rrb)
{
    extern __shared__ char smc[];
    int idx = blockIdx.x;
    int mode, m0, n0;
    const __nv_bfloat16 *Ah, *Al, *Bh, *Bl;
    if (idx < 1024) {        // KV: grid 16 x 64
        mode = 1; n0 = (idx & 15) * 128; m0 = (idx >> 4) * 128;
        Ah = g_w_hi; Al = g_w_lo; Bh = g_wkvt_hi; Bl = g_wkvt_lo;
    } else if (idx < 1280) { // Q: grid 8 x 32
        int r = idx - 1024;
        mode = 0; n0 = (r & 7) * 128; m0 = (r >> 3) * 128;
        Ah = g_w_hi; Al = g_w_lo; Bh = g_wqt_hi; Bl = g_wqt_lo;
    } else {                 // R: grid 8 x 16
        int r = idx - 1280;
        mode = 2; n0 = (r & 7) * 128; m0 = (r >> 3) * 128;
        Ah = g_r_hi; Al = g_r_lo; Bh = g_wrt_hi; Bl = g_wrt_lo;
    }
    hgemm_body(mode, m0, n0, Ah, Al, Bh, Bl, rwb, rrb, nullptr, smc);
}

__global__ void __launch_bounds__(256, 1)
hgemm_out(float* __restrict__ C)
{
    extern __shared__ char smc[];
    hgemm_body(3, blockIdx.y * 128, blockIdx.x * 128,
               g_av_hi, g_av_lo, g_wot_hi, g_wot_lo, nullptr, nullptr, C, smc);
}

// ---------------------------------------------------------------------------
// HMMA flash attention with relative shift, cp.async double-buffered.
// CTA: (bh, 64-query itile), 8 warps. Per 64-key tile:
//   S = Qw@K^T (MMA), T = Qr@Rw^T (MMA, 128-wide window),
//   T fragments SCATTER-ADD into S at c = c' + r - 63 (race-free: unique
//   writer per address, sync-separated from S writes), softmax, P split,
//   O += P@V (ldmatrix.trans).
// ---------------------------------------------------------------------------
constexpr int BUF_SZ = 73728;                    // K/V hi/lo + RW hi/lo
constexpr int oKH = 0, oKL = 9216, oVH = 18432, oVL = 27648;
constexpr int oRWH = 36864, oRWL = 55296;        // 128 x 144B
// Q staging reuses buffer 1 (consumed into registers before buf1 first write)
constexpr int sQWH = BUF_SZ + 0, sQWL = BUF_SZ + 9216;
constexpr int sQRH = BUF_SZ + 18432, sQRL = BUF_SZ + 27648;
constexpr int sS  = 147456;                      // 64 x 68 f32
constexpr int sPH = 164864, sPL = 174080;        // 64 x 72 bf16 each
constexpr int sCO = 183296, sLS = 183552;
constexpr int ATTN_SMEM = 183808;

__global__ void __launch_bounds__(256, 1) attn2()
{
    extern __shared__ char smc[];
    const uint32_t sb = smem_to_u32(smc);
    const int tid = threadIdx.x, lane = tid & 31, wid = tid >> 5;
    const int wm = wid >> 1, wn = wid & 1;
    const int itile = 15 - (blockIdx.x & 15);  // heavy tiles first
    const int bh = blockIdx.x >> 4;
    const int head = bh & 15, bb = bh >> 4;
    const int i0 = itile * 64;
    const int ntiles = itile + 17;

    auto issue_tile = [&](int t) {
        const int j0 = t * 64;
        const uint32_t s0 = sb + (t & 1) * BUF_SZ;
#pragma unroll
        for (int it = 0; it < 2; it++) {
            int u = tid + it * 256;
            int row = u >> 3, kk = (u & 7) * 8;
            uint32_t so = row * 144 + kk * 2;
            size_t off = ((size_t)bh * KLEN + j0 + row) * DH + kk;
            CP16(s0 + oKH + so, g_k_hi + off);
            CP16(s0 + oKL + so, g_k_lo + off);
            CP16(s0 + oVH + so, g_v_hi + off);
            CP16(s0 + oVL + so, g_v_lo + off);
        }
        const int dbase = j0 - i0 + 960;
#pragma unroll
        for (int it = 0; it < 4; it++) {
            int u = tid + it * 256;
            int row = u >> 3, kk = (u & 7) * 8;
            int dr = dbase + row;
            dr = dr < 0 ? 0 : (dr > KLEN - 1 ? KLEN - 1 : dr); // OOB rows masked later
            uint32_t so = row * 144 + kk * 2;
            size_t off = ((size_t)head * KLEN + dr) * DH + kk;
            CP16(s0 + oRWH + so, g_rk_hi + off);
            CP16(s0 + oRWL + so, g_rk_lo + off);
        }
        CP_COMMIT();
    };

    // prologue: tile0 in flight, Q staged into buf1 region, cached to regs
    issue_tile(0);
#pragma unroll
    for (int it = 0; it < 2; it++) {
        int u = tid + it * 256;
        int row = u >> 3, kk = (u & 7) * 8;
        uint32_t so = row * 144 + kk * 2;
        size_t off = ((size_t)bh * QLEN + i0 + row) * DH + kk;
        *(uint4*)(smc + sQWH + so) = *(const uint4*)(g_qw_hi + off);
        *(uint4*)(smc + sQWL + so) = *(const uint4*)(g_qw_lo + off);
        *(uint4*)(smc + sQRH + so) = *(const uint4*)(g_qr_hi + off);
        *(uint4*)(smc + sQRL + so) = *(const uint4*)(g_qr_lo + off);
    }
    __syncthreads();

    uint32_t qwh[4][4], qwl[4][4], qrh[4][4], qrl[4][4];
    {
        uint32_t ab = sb + sQWH + (wm * 16 + (lane & 15)) * 144 + ((lane >> 4) * 8) * 2;
#pragma unroll
        for (int kk = 0; kk < 4; kk++) {
            ldsm4(qwh[kk], ab + kk * 32);
            ldsm4(qwl[kk], ab + 9216 + kk * 32);
            ldsm4(qrh[kk], ab + 18432 + kk * 32);
            ldsm4(qrl[kk], ab + 27648 + kk * 32);
        }
    }
    __syncthreads();           // Q fully consumed -> buf1 reusable
    if (ntiles > 1) issue_tile(1);

    float o[4][4];
#pragma unroll
    for (int a = 0; a < 4; a++)
#pragma unroll
        for (int b = 0; b < 4; b++) o[a][b] = 0.f;
    float mrow = -3.0e38f, lrow = 0.f;
    const int srow = tid >> 2, sc0 = (tid & 3) * 16;

#pragma unroll 1
    for (int t = 0; t < ntiles; t++) {
        const int j0 = t * 64;
        const uint32_t s0 = sb + (t & 1) * BUF_SZ;
        if (t + 1 < ntiles) { CP_WAIT1(); } else { CP_WAIT0(); }
        __syncthreads();       // buffer t ready for everyone

        // ---- phase A: S = Qw@K^T, T = Qr@Rw^T ----
        float sacc[4][4], tacc[8][4];
#pragma unroll
        for (int a = 0; a < 4; a++)
#pragma unroll
            for (int b = 0; b < 4; b++) sacc[a][b] = 0.f;
#pragma unroll
        for (int a = 0; a < 8; a++)
#pragma unroll
            for (int b = 0; b < 4; b++) tacc[a][b] = 0.f;
        {
            const uint32_t kb = s0 + oKH + (lane & 7) * 144 + (((lane >> 3) & 1) * 8) * 2;
            const uint32_t rb = s0 + oRWH + (lane & 7) * 144 + (((lane >> 3) & 1) * 8) * 2;
#pragma unroll
            for (int kk = 0; kk < 4; kk++) {
#pragma unroll
                for (int ns = 0; ns < 4; ns++) {
                    uint32_t ba = kb + (wn * 32 + ns * 8) * 144 + kk * 32;
                    uint32_t bh2[2], bl2[2];
                    ldsm2(bh2, ba);
                    ldsm2(bl2, ba + 9216);
                    mma16816(sacc[ns], qwh[kk], bh2);
                    mma16816(sacc[ns], qwh[kk], bl2);
                    mma16816(sacc[ns], qwl[kk], bh2);
                }
#pragma unroll
                for (int ns = 0; ns < 8; ns++) {
                    uint32_t ba = rb + (wn * 64 + ns * 8) * 144 + kk * 32;
                    uint32_t bh2[2], bl2[2];
                    ldsm2(bh2, ba);
                    ldsm2(bl2, ba + 18432);
                    mma16816(tacc[ns], qrh[kk], bh2);
                    mma16816(tacc[ns], qrh[kk], bl2);
                    mma16816(tacc[ns], qrl[kk], bh2);
                }
            }
        }
        // write S fragments
        {
            float* Sf = (float*)(smc + sS);
            int r0 = wm * 16 + (lane >> 2);
#pragma unroll
            for (int ns = 0; ns < 4; ns++) {
                int c = wn * 32 + ns * 8 + (lane & 3) * 2;
                *(float2*)&Sf[r0 * 68 + c]       = make_float2(sacc[ns][0], sacc[ns][1]);
                *(float2*)&Sf[(r0 + 8) * 68 + c] = make_float2(sacc[ns][2], sacc[ns][3]);
            }
        }
        __syncthreads();

        // ---- phase B: scatter-add T fragments into S at c = c' + r - 63 ----
        {
            float* Sf = (float*)(smc + sS);
            int r0 = wm * 16 + (lane >> 2);
            int cb = wn * 64 + (lane & 3) * 2 - 63;
#pragma unroll
            for (int ns = 0; ns < 8; ns++) {
#pragma unroll
                for (int h = 0; h < 2; h++) {
                    int r = r0 + h * 8;
                    int c0 = cb + ns * 8 + r;
                    if (c0 >= 0 && c0 < 64) Sf[r * 68 + c0] += tacc[ns][h * 2 + 0];
                    int c1 = c0 + 1;
                    if (c1 >= 0 && c1 < 64) Sf[r * 68 + c1] += tacc[ns][h * 2 + 1];
                }
            }
        }
        __syncthreads();

        // ---- phase C: softmax (4 threads per row, 16 cols each) ----
        {
            const float* Sf = (const float*)(smc + sS);
            const int gi = i0 + srow;
            float sv[16];
            float mt = -3.0e38f;
#pragma unroll
            for (int c2 = 0; c2 < 16; c2++) {
                int c = sc0 + c2;
                float s = Sf[srow * 68 + c] * 0.125f;
                s = ((j0 + c) > gi + 1024) ? -1.0e30f : s;
                sv[c2] = s;
                mt = fmaxf(mt, s);
            }
            mt = fmaxf(mt, __shfl_xor_sync(0xffffffffu, mt, 1));
            mt = fmaxf(mt, __shfl_xor_sync(0xffffffffu, mt, 2));
            float mn = fmaxf(mrow, mt);
            float co = __expf(mrow - mn);
            mrow = mn;
            float rs = 0.f;
            __nv_bfloat16* Ph = (__nv_bfloat16*)(smc + sPH);
            __nv_bfloat16* Pl = (__nv_bfloat16*)(smc + sPL);
#pragma unroll
            for (int c2 = 0; c2 < 16; c2 += 2) {
                float p0 = __expf(sv[c2] - mn);
                float p1 = __expf(sv[c2 + 1] - mn);
                rs += p0 + p1;
                __nv_bfloat16 h0 = __float2bfloat16(p0), h1 = __float2bfloat16(p1);
                __nv_bfloat162 h2; h2.x = h0; h2.y = h1;
                __nv_bfloat162 l2;
                l2.x = __float2bfloat16(p0 - __bfloat162float(h0));
                l2.y = __float2bfloat16(p1 - __bfloat162float(h1));
                int c = sc0 + c2;
                *(__nv_bfloat162*)&Ph[srow * 72 + c] = h2;
                *(__nv_bfloat162*)&Pl[srow * 72 + c] = l2;
            }
            rs += __shfl_xor_sync(0xffffffffu, rs, 1);
            rs += __shfl_xor_sync(0xffffffffu, rs, 2);
            lrow = lrow * co + rs;
            if ((tid & 3) == 0) ((float*)(smc + sCO))[srow] = co;
        }
        __syncthreads();

        // ---- phase D: O = O*co + P @ V ----
        {
            float co0 = ((float*)(smc + sCO))[wm * 16 + (lane >> 2)];
            float co1 = ((float*)(smc + sCO))[wm * 16 + (lane >> 2) + 8];
#pragma unroll
            for (int ns = 0; ns < 4; ns++) {
                o[ns][0] *= co0; o[ns][1] *= co0;
                o[ns][2] *= co1; o[ns][3] *= co1;
            }
            const uint32_t pb = sb + sPH + (wm * 16 + (lane & 15)) * 144
                              + ((lane >> 4) * 8) * 2;
            const uint32_t vb = s0 + oVH + (lane & 15) * 144 + (wn * 32) * 2;
#pragma unroll
            for (int kk = 0; kk < 4; kk++) {
                uint32_t pah[4], pal[4];
                ldsm4(pah, pb + kk * 32);
                ldsm4(pal, pb + 9216 + kk * 32);
#pragma unroll
                for (int ns = 0; ns < 4; ns++) {
                    uint32_t va = vb + kk * 16 * 144 + ns * 8 * 2;
                    uint32_t vh2[2], vl2[2];
                    ldsm2t(vh2, va);
                    ldsm2t(vl2, va + 9216);
                    mma16816(o[ns], pah, vh2);
                    mma16816(o[ns], pah, vl2);
                    mma16816(o[ns], pal, vh2);
                }
            }
        }
        __syncthreads();       // buffer t & P fully consumed
        if (t + 2 < ntiles) issue_tile(t + 2);
    }

    // ---- finalize: O / l, split to bf16, write [b, i, head*64+d] ----
    if ((tid & 3) == 0) ((float*)(smc + sLS))[srow] = lrow;
    __syncthreads();
    {
        float li0 = 1.f / ((float*)(smc + sLS))[wm * 16 + (lane >> 2)];
        float li1 = 1.f / ((float*)(smc + sLS))[wm * 16 + (lane >> 2) + 8];
        int gi0 = i0 + wm * 16 + (lane >> 2);
#pragma unroll
        for (int ns = 0; ns < 4; ns++) {
            int d = wn * 32 + ns * 8 + (lane & 3) * 2;
            size_t off0 = ((size_t)bb * QLEN + gi0) * DM + head * DH + d;
            store_split2(g_av_hi, g_av_lo, off0, o[ns][0] * li0, o[ns][1] * li0);
            store_split2(g_av_hi, g_av_lo, off0 + 8 * DM, o[ns][2] * li1, o[ns][3] * li1);
        }
    }
}

// ---------------------------------------------------------------------------
extern "C" void kernel_launch(void* const* d_in, const int* in_sizes, int n_in,
                              void* d_out, int out_size)
{
    const float* w   = (const float*)d_in[0];
    const float* r   = (const float*)d_in[1];
    const float* rwb = (const float*)d_in[2];
    const float* rrb = (const float*)d_in[3];
    const float* Wq  = (const float*)d_in[4];
    const float* Wkv = (const float*)d_in[5];
    const float* Wr  = (const float*)d_in[6];
    const float* Wo  = (const float*)d_in[7];
    float* out = (float*)d_out;

    // pre-pass: split inputs, transpose+split weights
    convert_split<0><<<(BSZ * KLEN * DM) / 1024, 256>>>(w);
    convert_split<1><<<(KLEN * DM) / 1024, 256>>>(r);
    transpose_split<0><<<dim3(DM / 32, DM / 32), dim3(32, 8)>>>(Wq, DM);
    transpose_split<1><<<dim3(2 * DM / 32, DM / 32), dim3(32, 8)>>>(Wkv, 2 * DM);
    transpose_split<2><<<dim3(DM / 32, DM / 32), dim3(32, 8)>>>(Wr, DM);
    transpose_split<3><<<dim3(DM / 32, DM / 32), dim3(32, 8)>>>(Wo, DM);

    cudaFuncSetAttribute(hgemm_proj, cudaFuncAttributeMaxDynamicSharedMemorySize, GEMM_SMEM);
    cudaFuncSetAttribute(hgemm_out,  cudaFuncAttributeMaxDynamicSharedMemorySize, GEMM_SMEM);
    cudaFuncSetAttribute(attn2, cudaFuncAttributeMaxDynamicSharedMemorySize, ATTN_SMEM);

    // merged projections: 1024 (KV) + 256 (Q) + 128 (R) CTAs
    hgemm_proj<<<1408, 256, GEMM_SMEM>>>(rwb, rrb);

    // fused relative attention
    attn2<<<BSZ * NH * (QLEN / 64), 256, ATTN_SMEM>>>();

    // output projection
    hgemm_out<<<dim3(DM / 128, (BSZ * QLEN) / 128), 256, GEMM_SMEM>>>(out);
}

// round 7
// speedup vs baseline: 3.2945x; 1.0024x over previous
#include <cuda_runtime.h>
#include <cuda_bf16.h>
#include <cstdint>
#include <cstddef>

// ---------------------------------------------------------------------------
// Transformer-XL relative attention — all matmuls via mma.sync m16n8k16 bf16
// (hi/lo split, fp32 accum). tcgen05 unavailable (harness targets plain sm_103).
//
// rel_shift identity: for j <= i + 1024,
//   shift(BD)[b,i,j,n] = (q + r_r_bias) . rk[j - i + 1023, n, :]
//
// R7: term-major MMA issue order (break same-accumulator RAW chains),
//     Q in dedicated smem, merged prepasses.
// ---------------------------------------------------------------------------

constexpr int BSZ = 4, QLEN = 1024, KLEN = 2048, NH = 16, DH = 64, DM = 1024;

// ---- bf16 split global scratch --------------------------------------------
__device__ __nv_bfloat16 g_w_hi [(size_t)BSZ * KLEN * DM];
__device__ __nv_bfloat16 g_w_lo [(size_t)BSZ * KLEN * DM];
__device__ __nv_bfloat16 g_r_hi [(size_t)KLEN * DM];
__device__ __nv_bfloat16 g_r_lo [(size_t)KLEN * DM];
__device__ __nv_bfloat16 g_wqt_hi [(size_t)DM * DM],     g_wqt_lo [(size_t)DM * DM];
__device__ __nv_bfloat16 g_wkvt_hi[(size_t)2 * DM * DM], g_wkvt_lo[(size_t)2 * DM * DM];
__device__ __nv_bfloat16 g_wrt_hi [(size_t)DM * DM],     g_wrt_lo [(size_t)DM * DM];
__device__ __nv_bfloat16 g_wot_hi [(size_t)DM * DM],     g_wot_lo [(size_t)DM * DM];
__device__ __nv_bfloat16 g_qw_hi[(size_t)BSZ * NH * QLEN * DH], g_qw_lo[(size_t)BSZ * NH * QLEN * DH];
__device__ __nv_bfloat16 g_qr_hi[(size_t)BSZ * NH * QLEN * DH], g_qr_lo[(size_t)BSZ * NH * QLEN * DH];
__device__ __nv_bfloat16 g_k_hi [(size_t)BSZ * NH * KLEN * DH], g_k_lo [(size_t)BSZ * NH * KLEN * DH];
__device__ __nv_bfloat16 g_v_hi [(size_t)BSZ * NH * KLEN * DH], g_v_lo [(size_t)BSZ * NH * KLEN * DH];
__device__ __nv_bfloat16 g_rk_hi[(size_t)NH * KLEN * DH],       g_rk_lo[(size_t)NH * KLEN * DH];
__device__ __nv_bfloat16 g_av_hi[(size_t)BSZ * QLEN * DM], g_av_lo[(size_t)BSZ * QLEN * DM];

// ---------------------------------------------------------------------------
// helpers
// ---------------------------------------------------------------------------
__device__ __forceinline__ uint32_t smem_to_u32(const void* p) {
    uint32_t a;
    asm("{ .reg .u64 t; cvta.to.shared.u64 t, %1; cvt.u32.u64 %0, t; }"
        : "=r"(a) : "l"(p));
    return a;
}
__device__ __forceinline__ void ldsm4(uint32_t* r, uint32_t a) {
    asm volatile("ldmatrix.sync.aligned.m8n8.x4.shared.b16 {%0,%1,%2,%3}, [%4];"
                 : "=r"(r[0]), "=r"(r[1]), "=r"(r[2]), "=r"(r[3]) : "r"(a));
}
__device__ __forceinline__ void ldsm2(uint32_t* r, uint32_t a) {
    asm volatile("ldmatrix.sync.aligned.m8n8.x2.shared.b16 {%0,%1}, [%2];"
                 : "=r"(r[0]), "=r"(r[1]) : "r"(a));
}
__device__ __forceinline__ void ldsm2t(uint32_t* r, uint32_t a) {
    asm volatile("ldmatrix.sync.aligned.m8n8.x2.trans.shared.b16 {%0,%1}, [%2];"
                 : "=r"(r[0]), "=r"(r[1]) : "r"(a));
}
__device__ __forceinline__ void mma16816(float* d, const uint32_t* a, const uint32_t* b) {
    asm volatile("mma.sync.aligned.m16n8k16.row.col.f32.bf16.bf16.f32 "
                 "{%0,%1,%2,%3}, {%4,%5,%6,%7}, {%8,%9}, {%0,%1,%2,%3};"
                 : "+f"(d[0]), "+f"(d[1]), "+f"(d[2]), "+f"(d[3])
                 : "r"(a[0]), "r"(a[1]), "r"(a[2]), "r"(a[3]),
                   "r"(b[0]), "r"(b[1]));
}
#define CP16(sm, gm) \
    asm volatile("cp.async.cg.shared.global [%0], [%1], 16;" :: "r"(sm), "l"(gm))
#define CP_COMMIT() asm volatile("cp.async.commit_group;" ::: "memory")
#define CP_WAIT1()  asm volatile("cp.async.wait_group 1;" ::: "memory")
#define CP_WAIT0()  asm volatile("cp.async.wait_group 0;" ::: "memory")

__device__ __forceinline__ void store_split2(__nv_bfloat16* hi, __nv_bfloat16* lo,
                                             size_t off, float x, float y) {
    __nv_bfloat16 hx = __float2bfloat16(x), hy = __float2bfloat16(y);
    __nv_bfloat16 lx = __float2bfloat16(x - __bfloat162float(hx));
    __nv_bfloat16 ly = __float2bfloat16(y - __bfloat162float(hy));
    __nv_bfloat162 h2; h2.x = hx; h2.y = hy;
    __nv_bfloat162 l2; l2.x = lx; l2.y = ly;
    *(__nv_bfloat162*)(hi + off) = h2;
    *(__nv_bfloat162*)(lo + off) = l2;
}

// ---------------------------------------------------------------------------
// Pre-pass 1 (merged): fp32 -> bf16 hi/lo split for w and r.
// ---------------------------------------------------------------------------
constexpr size_t W_UNITS = (size_t)BSZ * KLEN * DM / 4;  // 2,097,152
constexpr size_t R_UNITS = (size_t)KLEN * DM / 4;        //   524,288

__global__ void convert_all(const float* __restrict__ w, const float* __restrict__ r) {
    size_t u = (size_t)blockIdx.x * blockDim.x + threadIdx.x;
    const float* s;
    __nv_bfloat16 *hi, *lo;
    size_t base;
    if (u < W_UNITS) { s = w; hi = g_w_hi; lo = g_w_lo; base = u; }
    else             { s = r; hi = g_r_hi; lo = g_r_lo; base = u - W_UNITS; }
    size_t i = base * 4;
    float4 v = *(const float4*)(s + i);
    float vv[4] = {v.x, v.y, v.z, v.w};
    __nv_bfloat16 h[4], l[4];
#pragma unroll
    for (int j = 0; j < 4; j++) {
        h[j] = __float2bfloat16(vv[j]);
        l[j] = __float2bfloat16(vv[j] - __bfloat162float(h[j]));
    }
    *(uint2*)(hi + i) = *(uint2*)h;
    *(uint2*)(lo + i) = *(uint2*)l;
}

// ---------------------------------------------------------------------------
// Pre-pass 2 (merged): all 4 weight transposes. W [K][N] fp32 -> [N][K] bf16.
// flat grid: [0,1024) Wq, [1024,3072) Wkv, [3072,4096) Wr, [4096,5120) Wo
// ---------------------------------------------------------------------------
__global__ void transpose_all(const float* __restrict__ Wq, const float* __restrict__ Wkv,
                              const float* __restrict__ Wr, const float* __restrict__ Wo) {
    __shared__ float t[32][33];
    int idx = blockIdx.x;
    const float* W;
    __nv_bfloat16 *hi, *lo;
    int N, n0, k0;
    if (idx < 1024) {
        W = Wq; hi = g_wqt_hi; lo = g_wqt_lo; N = DM;
        n0 = (idx & 31) * 32; k0 = (idx >> 5) * 32;
    } else if (idx < 3072) {
        int lidx = idx - 1024;
        W = Wkv; hi = g_wkvt_hi; lo = g_wkvt_lo; N = 2 * DM;
        n0 = (lidx & 63) * 32; k0 = (lidx >> 6) * 32;
    } else if (idx < 4096) {
        int lidx = idx - 3072;
        W = Wr; hi = g_wrt_hi; lo = g_wrt_lo; N = DM;
        n0 = (lidx & 31) * 32; k0 = (lidx >> 5) * 32;
    } else {
        int lidx = idx - 4096;
        W = Wo; hi = g_wot_hi; lo = g_wot_lo; N = DM;
        n0 = (lidx & 31) * 32; k0 = (lidx >> 5) * 32;
    }
    int tx = threadIdx.x, ty = threadIdx.y;
#pragma unroll
    for (int i = 0; i < 4; i++)
        t[ty + 8 * i][tx] = W[(size_t)(k0 + ty + 8 * i) * N + n0 + tx];
    __syncthreads();
#pragma unroll
    for (int i = 0; i < 4; i++) {
        float v = t[tx][ty + 8 * i];
        __nv_bfloat16 h = __float2bfloat16(v);
        __nv_bfloat16 l = __float2bfloat16(v - __bfloat162float(h));
        size_t o = (size_t)(n0 + ty + 8 * i) * DM + k0 + tx;
        hi[o] = h;
        lo[o] = l;
    }
}

// ---------------------------------------------------------------------------
// HMMA split-bf16 GEMM body. 128x128 tile, 8 warps (32x64 warp tile),
// cp.async double-buffered chunks of 64 along K=1024.
// Term-major MMA order: all B frags loaded, then hh x16, hl x16, lh x16.
// mode: 0 -> Qw/Qr(+bias), 1 -> K/V, 2 -> rk, 3 -> fp32 C (d_out)
// ---------------------------------------------------------------------------
constexpr int GEMM_BUF = 73728;          // 4 arrays * 128 rows * 144B
constexpr int GEMM_SMEM = 2 * GEMM_BUF;  // 147456

__device__ __forceinline__ void hgemm_body(
    int mode, int m0, int n0,
    const __nv_bfloat16* __restrict__ Ah, const __nv_bfloat16* __restrict__ Al,
    const __nv_bfloat16* __restrict__ Bh, const __nv_bfloat16* __restrict__ Bl,
    const float* __restrict__ rwb, const float* __restrict__ rrb,
    float* __restrict__ C, char* smc)
{
    const uint32_t sb = smem_to_u32(smc);
    const int tid = threadIdx.x, lane = tid & 31, wid = tid >> 5;
    const int wm = wid >> 1, wn = wid & 1;

    float acc[2][8][4];
#pragma unroll
    for (int a = 0; a < 2; a++)
#pragma unroll
        for (int b = 0; b < 8; b++)
#pragma unroll
            for (int c = 0; c < 4; c++) acc[a][b][c] = 0.f;

    auto load_chunk = [&](int c, int buf) {
        const int k0 = c * 64;
        const uint32_t s0 = sb + buf * GEMM_BUF;
#pragma unroll
        for (int it = 0; it < 4; it++) {
            int u = tid + it * 256;
            int row = u >> 3, kk = (u & 7) * 8;
            uint32_t so = row * 144 + kk * 2;
            int am = m0 + row;
            int grow = (mode == 0) ? (((am >> 10) << 11) + QLEN + (am & (QLEN - 1))) : am;
            size_t ao = (size_t)grow * DM + k0 + kk;
            size_t bo = (size_t)(n0 + row) * DM + k0 + kk;
            CP16(s0 + so,         Ah + ao);
            CP16(s0 + 18432 + so, Al + ao);
            CP16(s0 + 36864 + so, Bh + bo);
            CP16(s0 + 55296 + so, Bl + bo);
        }
        CP_COMMIT();
    };

    load_chunk(0, 0);
#pragma unroll 1
    for (int c = 0; c < 16; c++) {
        if (c + 1 < 16) { load_chunk(c + 1, (c + 1) & 1); CP_WAIT1(); }
        else            { CP_WAIT0(); }
        __syncthreads();
        const uint32_t s0 = sb + (c & 1) * GEMM_BUF;
        const uint32_t aBase = s0 + (wm * 32 + (lane & 15)) * 144 + ((lane >> 4) * 8) * 2;
        const uint32_t bBase = s0 + 36864 + (wn * 64 + (lane & 7)) * 144
                             + (((lane >> 3) & 1) * 8) * 2;
#pragma unroll
        for (int kk = 0; kk < 4; kk++) {
            uint32_t ah[2][4], al[2][4];
#pragma unroll
            for (int ms = 0; ms < 2; ms++) {
                uint32_t aa = aBase + ms * 16 * 144 + kk * 32;
                ldsm4(ah[ms], aa);
                ldsm4(al[ms], aa + 18432);
            }
            uint32_t bh[8][2], bl[8][2];
#pragma unroll
            for (int ns = 0; ns < 8; ns++) {
                uint32_t ba = bBase + ns * 8 * 144 + kk * 32;
                ldsm2(bh[ns], ba);
                ldsm2(bl[ns], ba + 18432);
            }
            // term-major: reuse distance per accumulator = 16 MMAs
#pragma unroll
            for (int ns = 0; ns < 8; ns++)
#pragma unroll
                for (int ms = 0; ms < 2; ms++) mma16816(acc[ms][ns], ah[ms], bh[ns]);
#pragma unroll
            for (int ns = 0; ns < 8; ns++)
#pragma unroll
                for (int ms = 0; ms < 2; ms++) mma16816(acc[ms][ns], ah[ms], bl[ns]);
#pragma unroll
            for (int ns = 0; ns < 8; ns++)
#pragma unroll
                for (int ms = 0; ms < 2; ms++) mma16816(acc[ms][ns], al[ms], bh[ns]);
        }
        __syncthreads();
    }

    // epilogue
#pragma unroll
    for (int ms = 0; ms < 2; ms++) {
        int r0 = m0 + wm * 32 + ms * 16 + (lane >> 2);
#pragma unroll
        for (int ns = 0; ns < 8; ns++) {
            int col = n0 + wn * 64 + ns * 8 + (lane & 3) * 2;
#pragma unroll
            for (int h = 0; h < 2; h++) {
                int row = r0 + h * 8;
                float x = acc[ms][ns][h * 2 + 0];
                float y = acc[ms][ns][h * 2 + 1];
                if (mode == 0) {
                    int bb = row >> 10, ii = row & 1023;
                    int head = col >> 6, d = col & 63;
                    size_t off = (((size_t)(bb * NH + head)) * QLEN + ii) * DH + d;
                    store_split2(g_qw_hi, g_qw_lo, off, x + rwb[col], y + rwb[col + 1]);
                    store_split2(g_qr_hi, g_qr_lo, off, x + rrb[col], y + rrb[col + 1]);
                } else if (mode == 1) {
                    int bb = row >> 11, jj = row & 2047;
                    int cc = (col < DM) ? col : col - DM;
                    int head = cc >> 6, d = cc & 63;
                    size_t off = (((size_t)(bb * NH + head)) * KLEN + jj) * DH + d;
                    if (col < DM) store_split2(g_k_hi, g_k_lo, off, x, y);
                    else          store_split2(g_v_hi, g_v_lo, off, x, y);
                } else if (mode == 2) {
                    int head = col >> 6, d = col & 63;
                    size_t off = ((size_t)head * KLEN + row) * DH + d;
                    store_split2(g_rk_hi, g_rk_lo, off, x, y);
                } else {
                    *(float2*)(C + (size_t)row * DM + col) = make_float2(x, y);
                }
            }
        }
    }
}

// merged Q / KV / R projections: one launch, blockIdx-decoded mode
__global__ void __launch_bounds__(256, 1)
hgemm_proj(const float* __restrict__ rwb, const float* __restrict__ rrb)
{
    extern __shared__ char smc[];
    int idx = blockIdx.x;
    int mode, m0, n0;
    const __nv_bfloat16 *Ah, *Al, *Bh, *Bl;
    if (idx < 1024) {        // KV: grid 16 x 64
        mode = 1; n0 = (idx & 15) * 128; m0 = (idx >> 4) * 128;
        Ah = g_w_hi; Al = g_w_lo; Bh = g_wkvt_hi; Bl = g_wkvt_lo;
    } else if (idx < 1280) { // Q: grid 8 x 32
        int r = idx - 1024;
        mode = 0; n0 = (r & 7) * 128; m0 = (r >> 3) * 128;
        Ah = g_w_hi; Al = g_w_lo; Bh = g_wqt_hi; Bl = g_wqt_lo;
    } else {                 // R: grid 8 x 16
        int r = idx - 1280;
        mode = 2; n0 = (r & 7) * 128; m0 = (r >> 3) * 128;
        Ah = g_r_hi; Al = g_r_lo; Bh = g_wrt_hi; Bl = g_wrt_lo;
    }
    hgemm_body(mode, m0, n0, Ah, Al, Bh, Bl, rwb, rrb, nullptr, smc);
}

__global__ void __launch_bounds__(256, 1)
hgemm_out(float* __restrict__ C)
{
    extern __shared__ char smc[];
    hgemm_body(3, blockIdx.y * 128, blockIdx.x * 128,
               g_av_hi, g_av_lo, g_wot_hi, g_wot_lo, nullptr, nullptr, C, smc);
}

// ---------------------------------------------------------------------------
// HMMA flash attention with relative shift, cp.async double-buffered,
// term-major MMA issue. Q in dedicated smem (re-ldsm'd per k-step).
// ---------------------------------------------------------------------------
constexpr int BUF_SZ = 73728;                    // K/V hi/lo + RW hi/lo
constexpr int oKH = 0, oKL = 9216, oVH = 18432, oVL = 27648;
constexpr int oRWH = 36864, oRWL = 55296;        // 128 x 144B
constexpr int sQWH = 147456, sQWL = 156672, sQRH = 165888, sQRL = 175104;
constexpr int sS  = 184320;                      // 64 x 68 f32 (17408 B)
constexpr int sPH = 201728, sPL = 210944;        // 64 x 72 bf16 each
constexpr int sCO = 220160, sLS = 220416;
constexpr int ATTN_SMEM = 220672;

__global__ void __launch_bounds__(256, 1) attn2()
{
    extern __shared__ char smc[];
    const uint32_t sb = smem_to_u32(smc);
    const int tid = threadIdx.x, lane = tid & 31, wid = tid >> 5;
    const int wm = wid >> 1, wn = wid & 1;
    const int itile = 15 - (blockIdx.x & 15);  // heavy tiles first
    const int bh = blockIdx.x >> 4;
    const int head = bh & 15, bb = bh >> 4;
    const int i0 = itile * 64;
    const int ntiles = itile + 17;

    auto issue_tile = [&](int t) {
        const int j0 = t * 64;
        const uint32_t s0 = sb + (t & 1) * BUF_SZ;
#pragma unroll
        for (int it = 0; it < 2; it++) {
            int u = tid + it * 256;
            int row = u >> 3, kk = (u & 7) * 8;
            uint32_t so = row * 144 + kk * 2;
            size_t off = ((size_t)bh * KLEN + j0 + row) * DH + kk;
            CP16(s0 + oKH + so, g_k_hi + off);
            CP16(s0 + oKL + so, g_k_lo + off);
            CP16(s0 + oVH + so, g_v_hi + off);
            CP16(s0 + oVL + so, g_v_lo + off);
        }
        const int dbase = j0 - i0 + 960;
#pragma unroll
        for (int it = 0; it < 4; it++) {
            int u = tid + it * 256;
            int row = u >> 3, kk = (u & 7) * 8;
            int dr = dbase + row;
            dr = dr < 0 ? 0 : (dr > KLEN - 1 ? KLEN - 1 : dr); // OOB rows masked later
            uint32_t so = row * 144 + kk * 2;
            size_t off = ((size_t)head * KLEN + dr) * DH + kk;
            CP16(s0 + oRWH + so, g_rk_hi + off);
            CP16(s0 + oRWL + so, g_rk_lo + off);
        }
        CP_COMMIT();
    };

    // prologue: tile0 + tile1 in flight, Q staged to dedicated smem
    issue_tile(0);
#pragma unroll
    for (int it = 0; it < 2; it++) {
        int u = tid + it * 256;
        int row = u >> 3, kk = (u & 7) * 8;
        uint32_t so = row * 144 + kk * 2;
        size_t off = ((size_t)bh * QLEN + i0 + row) * DH + kk;
        *(uint4*)(smc + sQWH + so) = *(const uint4*)(g_qw_hi + off);
        *(uint4*)(smc + sQWL + so) = *(const uint4*)(g_qw_lo + off);
        *(uint4*)(smc + sQRH + so) = *(const uint4*)(g_qr_hi + off);
        *(uint4*)(smc + sQRL + so) = *(const uint4*)(g_qr_lo + off);
    }
    if (ntiles > 1) issue_tile(1);
    __syncthreads();           // Q visible to all warps

    float o[4][4];
#pragma unroll
    for (int a = 0; a < 4; a++)
#pragma unroll
        for (int b = 0; b < 4; b++) o[a][b] = 0.f;
    float mrow = -3.0e38f, lrow = 0.f;
    const int srow = tid >> 2, sc0 = (tid & 3) * 16;

#pragma unroll 1
    for (int t = 0; t < ntiles; t++) {
        const int j0 = t * 64;
        const uint32_t s0 = sb + (t & 1) * BUF_SZ;
        if (t + 1 < ntiles) { CP_WAIT1(); } else { CP_WAIT0(); }
        __syncthreads();       // buffer t ready for everyone

        // ---- phase A: S = Qw@K^T, T = Qr@Rw^T (term-major issue) ----
        float sacc[4][4], tacc[8][4];
#pragma unroll
        for (int a = 0; a < 4; a++)
#pragma unroll
            for (int b = 0; b < 4; b++) sacc[a][b] = 0.f;
#pragma unroll
        for (int a = 0; a < 8; a++)
#pragma unroll
            for (int b = 0; b < 4; b++) tacc[a][b] = 0.f;
        {
            const uint32_t qb = sb + sQWH + (wm * 16 + (lane & 15)) * 144
                              + ((lane >> 4) * 8) * 2;
            const uint32_t kb = s0 + oKH + (lane & 7) * 144 + (((lane >> 3) & 1) * 8) * 2;
            const uint32_t rb = s0 + oRWH + (lane & 7) * 144 + (((lane >> 3) & 1) * 8) * 2;
#pragma unroll
            for (int kk = 0; kk < 4; kk++) {
                uint32_t qwh[4], qwl[4], qrh[4], qrl[4];
                ldsm4(qwh, qb + kk * 32);
                ldsm4(qwl, qb + 9216 + kk * 32);
                ldsm4(qrh, qb + 18432 + kk * 32);
                ldsm4(qrl, qb + 27648 + kk * 32);
                uint32_t kbh[4][2], kbl[4][2], rbh[8][2], rbl[8][2];
#pragma unroll
                for (int ns = 0; ns < 4; ns++) {
                    uint32_t ba = kb + (wn * 32 + ns * 8) * 144 + kk * 32;
                    ldsm2(kbh[ns], ba);
                    ldsm2(kbl[ns], ba + 9216);
                }
#pragma unroll
                for (int ns = 0; ns < 8; ns++) {
                    uint32_t ba = rb + (wn * 64 + ns * 8) * 144 + kk * 32;
                    ldsm2(rbh[ns], ba);
                    ldsm2(rbl[ns], ba + 18432);
                }
                // hh terms (12 independent)
#pragma unroll
                for (int ns = 0; ns < 4; ns++) mma16816(sacc[ns], qwh, kbh[ns]);
#pragma unroll
                for (int ns = 0; ns < 8; ns++) mma16816(tacc[ns], qrh, rbh[ns]);
                // hl terms
#pragma unroll
                for (int ns = 0; ns < 4; ns++) mma16816(sacc[ns], qwh, kbl[ns]);
#pragma unroll
                for (int ns = 0; ns < 8; ns++) mma16816(tacc[ns], qrh, rbl[ns]);
                // lh terms
#pragma unroll
                for (int ns = 0; ns < 4; ns++) mma16816(sacc[ns], qwl, kbh[ns]);
#pragma unroll
                for (int ns = 0; ns < 8; ns++) mma16816(tacc[ns], qrl, rbh[ns]);
            }
        }
        // write S fragments
        {
            float* Sf = (float*)(smc + sS);
            int r0 = wm * 16 + (lane >> 2);
#pragma unroll
            for (int ns = 0; ns < 4; ns++) {
                int c = wn * 32 + ns * 8 + (lane & 3) * 2;
                *(float2*)&Sf[r0 * 68 + c]       = make_float2(sacc[ns][0], sacc[ns][1]);
                *(float2*)&Sf[(r0 + 8) * 68 + c] = make_float2(sacc[ns][2], sacc[ns][3]);
            }
        }
        __syncthreads();

        // ---- phase B: scatter-add T fragments into S at c = c' + r - 63 ----
        {
            float* Sf = (float*)(smc + sS);
            int r0 = wm * 16 + (lane >> 2);
            int cb = wn * 64 + (lane & 3) * 2 - 63;
#pragma unroll
            for (int ns = 0; ns < 8; ns++) {
#pragma unroll
                for (int h = 0; h < 2; h++) {
                    int r = r0 + h * 8;
                    int c0 = cb + ns * 8 + r;
                    if (c0 >= 0 && c0 < 64) Sf[r * 68 + c0] += tacc[ns][h * 2 + 0];
                    int c1 = c0 + 1;
                    if (c1 >= 0 && c1 < 64) Sf[r * 68 + c1] += tacc[ns][h * 2 + 1];
                }
            }
        }
        __syncthreads();

        // ---- phase C: softmax (4 threads per row, 16 cols each) ----
        {
            const float* Sf = (const float*)(smc + sS);
            const int gi = i0 + srow;
            float sv[16];
            float mt = -3.0e38f;
#pragma unroll
            for (int c2 = 0; c2 < 16; c2++) {
                int c = sc0 + c2;
                float s = Sf[srow * 68 + c] * 0.125f;
                s = ((j0 + c) > gi + 1024) ? -1.0e30f : s;
                sv[c2] = s;
                mt = fmaxf(mt, s);
            }
            mt = fmaxf(mt, __shfl_xor_sync(0xffffffffu, mt, 1));
            mt = fmaxf(mt, __shfl_xor_sync(0xffffffffu, mt, 2));
            float mn = fmaxf(mrow, mt);
            float co = __expf(mrow - mn);
            mrow = mn;
            float rs = 0.f;
            __nv_bfloat16* Ph = (__nv_bfloat16*)(smc + sPH);
            __nv_bfloat16* Pl = (__nv_bfloat16*)(smc + sPL);
#pragma unroll
            for (int c2 = 0; c2 < 16; c2 += 2) {
                float p0 = __expf(sv[c2] - mn);
                float p1 = __expf(sv[c2 + 1] - mn);
                rs += p0 + p1;
                __nv_bfloat16 h0 = __float2bfloat16(p0), h1 = __float2bfloat16(p1);
                __nv_bfloat162 h2; h2.x = h0; h2.y = h1;
                __nv_bfloat162 l2;
                l2.x = __float2bfloat16(p0 - __bfloat162float(h0));
                l2.y = __float2bfloat16(p1 - __bfloat162float(h1));
                int c = sc0 + c2;
                *(__nv_bfloat162*)&Ph[srow * 72 + c] = h2;
                *(__nv_bfloat162*)&Pl[srow * 72 + c] = l2;
            }
            rs += __shfl_xor_sync(0xffffffffu, rs, 1);
            rs += __shfl_xor_sync(0xffffffffu, rs, 2);
            lrow = lrow * co + rs;
            if ((tid & 3) == 0) ((float*)(smc + sCO))[srow] = co;
        }
        __syncthreads();

        // ---- phase D: O = O*co + P @ V (term-major) ----
        {
            float co0 = ((float*)(smc + sCO))[wm * 16 + (lane >> 2)];
            float co1 = ((float*)(smc + sCO))[wm * 16 + (lane >> 2) + 8];
#pragma unroll
            for (int ns = 0; ns < 4; ns++) {
                o[ns][0] *= co0; o[ns][1] *= co0;
                o[ns][2] *= co1; o[ns][3] *= co1;
            }
            const uint32_t pb = sb + sPH + (wm * 16 + (lane & 15)) * 144
                              + ((lane >> 4) * 8) * 2;
            const uint32_t vb = s0 + oVH + (lane & 15) * 144 + (wn * 32) * 2;
#pragma unroll
            for (int kk = 0; kk < 4; kk++) {
                uint32_t pah[4], pal[4];
                ldsm4(pah, pb + kk * 32);
                ldsm4(pal, pb + 9216 + kk * 32);
                uint32_t vh[4][2], vl[4][2];
#pragma unroll
                for (int ns = 0; ns < 4; ns++) {
                    uint32_t va = vb + kk * 16 * 144 + ns * 8 * 2;
                    ldsm2t(vh[ns], va);
                    ldsm2t(vl[ns], va + 9216);
                }
#pragma unroll
                for (int ns = 0; ns < 4; ns++) mma16816(o[ns], pah, vh[ns]);
#pragma unroll
                for (int ns = 0; ns < 4; ns++) mma16816(o[ns], pah, vl[ns]);
#pragma unroll
                for (int ns = 0; ns < 4; ns++) mma16816(o[ns], pal, vh[ns]);
            }
        }
        __syncthreads();       // buffer t & P fully consumed
        if (t + 2 < ntiles) issue_tile(t + 2);
    }

    // ---- finalize: O / l, split to bf16, write [b, i, head*64+d] ----
    if ((tid & 3) == 0) ((float*)(smc + sLS))[srow] = lrow;
    __syncthreads();
    {
        float li0 = 1.f / ((float*)(smc + sLS))[wm * 16 + (lane >> 2)];
        float li1 = 1.f / ((float*)(smc + sLS))[wm * 16 + (lane >> 2) + 8];
        int gi0 = i0 + wm * 16 + (lane >> 2);
#pragma unroll
        for (int ns = 0; ns < 4; ns++) {
            int d = wn * 32 + ns * 8 + (lane & 3) * 2;
            size_t off0 = ((size_t)bb * QLEN + gi0) * DM + head * DH + d;
            store_split2(g_av_hi, g_av_lo, off0, o[ns][0] * li0, o[ns][1] * li0);
            store_split2(g_av_hi, g_av_lo, off0 + 8 * DM, o[ns][2] * li1, o[ns][3] * li1);
        }
    }
}

// ---------------------------------------------------------------------------
extern "C" void kernel_launch(void* const* d_in, const int* in_sizes, int n_in,
                              void* d_out, int out_size)
{
    const float* w   = (const float*)d_in[0];
    const float* r   = (const float*)d_in[1];
    const float* rwb = (const float*)d_in[2];
    const float* rrb = (const float*)d_in[3];
    const float* Wq  = (const float*)d_in[4];
    const float* Wkv = (const float*)d_in[5];
    const float* Wr  = (const float*)d_in[6];
    const float* Wo  = (const float*)d_in[7];
    float* out = (float*)d_out;

    // merged pre-passes
    convert_all<<<(int)((W_UNITS + R_UNITS) / 256), 256>>>(w, r);
    transpose_all<<<5120, dim3(32, 8)>>>(Wq, Wkv, Wr, Wo);

    cudaFuncSetAttribute(hgemm_proj, cudaFuncAttributeMaxDynamicSharedMemorySize, GEMM_SMEM);
    cudaFuncSetAttribute(hgemm_out,  cudaFuncAttributeMaxDynamicSharedMemorySize, GEMM_SMEM);
    cudaFuncSetAttribute(attn2, cudaFuncAttributeMaxDynamicSharedMemorySize, ATTN_SMEM);

    // merged projections: 1024 (KV) + 256 (Q) + 128 (R) CTAs
    hgemm_proj<<<1408, 256, GEMM_SMEM>>>(rwb, rrb);

    // fused relative attention
    attn2<<<BSZ * NH * (QLEN / 64), 256, ATTN_SMEM>>>();

    // output projection
    hgemm_out<<<dim3(DM / 128, (BSZ * QLEN) / 128), 256, GEMM_SMEM>>>(out);
}

// round 11
// speedup vs baseline: 3.7365x; 1.1342x over previous
#include <cuda_runtime.h>
#include <cuda_bf16.h>
#include <cstdint>
#include <cstddef>

// ---------------------------------------------------------------------------
// Transformer-XL relative attention — all matmuls via mma.sync m16n8k16 bf16
// (hi/lo split, fp32 accum). tcgen05 unavailable (harness targets plain sm_103).
//
// rel_shift identity: for j <= i + 1024,
//   shift(BD)[b,i,j,n] = (q + r_r_bias) . rk[j - i + 1023, n, :]
//
// R8: attn BJ=128 (T-window flops -13%, syncs halved, ldsm.x4 B-frags,
//     swizzled 128B rows, region-phased cp.async prefetch);
//     hgemm single-buffer 73KB -> 2 CTAs/SM.
// ---------------------------------------------------------------------------

constexpr int BSZ = 4, QLEN = 1024, KLEN = 2048, NH = 16, DH = 64, DM = 1024;

// ---- bf16 split global scratch --------------------------------------------
__device__ __nv_bfloat16 g_w_hi [(size_t)BSZ * KLEN * DM];
__device__ __nv_bfloat16 g_w_lo [(size_t)BSZ * KLEN * DM];
__device__ __nv_bfloat16 g_r_hi [(size_t)KLEN * DM];
__device__ __nv_bfloat16 g_r_lo [(size_t)KLEN * DM];
__device__ __nv_bfloat16 g_wqt_hi [(size_t)DM * DM],     g_wqt_lo [(size_t)DM * DM];
__device__ __nv_bfloat16 g_wkvt_hi[(size_t)2 * DM * DM], g_wkvt_lo[(size_t)2 * DM * DM];
__device__ __nv_bfloat16 g_wrt_hi [(size_t)DM * DM],     g_wrt_lo [(size_t)DM * DM];
__device__ __nv_bfloat16 g_wot_hi [(size_t)DM * DM],     g_wot_lo [(size_t)DM * DM];
__device__ __nv_bfloat16 g_qw_hi[(size_t)BSZ * NH * QLEN * DH], g_qw_lo[(size_t)BSZ * NH * QLEN * DH];
__device__ __nv_bfloat16 g_qr_hi[(size_t)BSZ * NH * QLEN * DH], g_qr_lo[(size_t)BSZ * NH * QLEN * DH];
__device__ __nv_bfloat16 g_k_hi [(size_t)BSZ * NH * KLEN * DH], g_k_lo [(size_t)BSZ * NH * KLEN * DH];
__device__ __nv_bfloat16 g_v_hi [(size_t)BSZ * NH * KLEN * DH], g_v_lo [(size_t)BSZ * NH * KLEN * DH];
__device__ __nv_bfloat16 g_rk_hi[(size_t)NH * KLEN * DH],       g_rk_lo[(size_t)NH * KLEN * DH];
__device__ __nv_bfloat16 g_av_hi[(size_t)BSZ * QLEN * DM], g_av_lo[(size_t)BSZ * QLEN * DM];

// ---------------------------------------------------------------------------
// helpers
// ---------------------------------------------------------------------------
__device__ __forceinline__ uint32_t smem_to_u32(const void* p) {
    uint32_t a;
    asm("{ .reg .u64 t; cvta.to.shared.u64 t, %1; cvt.u32.u64 %0, t; }"
        : "=r"(a) : "l"(p));
    return a;
}
__device__ __forceinline__ uint32_t swz(uint32_t x) { return x ^ ((x >> 3) & 0x70); }

__device__ __forceinline__ void ldsm4(uint32_t* r, uint32_t a) {
    asm volatile("ldmatrix.sync.aligned.m8n8.x4.shared.b16 {%0,%1,%2,%3}, [%4];"
                 : "=r"(r[0]), "=r"(r[1]), "=r"(r[2]), "=r"(r[3]) : "r"(a));
}
__device__ __forceinline__ void ldsm2(uint32_t* r, uint32_t a) {
    asm volatile("ldmatrix.sync.aligned.m8n8.x2.shared.b16 {%0,%1}, [%2];"
                 : "=r"(r[0]), "=r"(r[1]) : "r"(a));
}
__device__ __forceinline__ void ldsm2t(uint32_t* r, uint32_t a) {
    asm volatile("ldmatrix.sync.aligned.m8n8.x2.trans.shared.b16 {%0,%1}, [%2];"
                 : "=r"(r[0]), "=r"(r[1]) : "r"(a));
}
__device__ __forceinline__ void mma16816(float* d, const uint32_t* a, const uint32_t* b) {
    asm volatile("mma.sync.aligned.m16n8k16.row.col.f32.bf16.bf16.f32 "
                 "{%0,%1,%2,%3}, {%4,%5,%6,%7}, {%8,%9}, {%0,%1,%2,%3};"
                 : "+f"(d[0]), "+f"(d[1]), "+f"(d[2]), "+f"(d[3])
                 : "r"(a[0]), "r"(a[1]), "r"(a[2]), "r"(a[3]),
                   "r"(b[0]), "r"(b[1]));
}
#define CP16(sm, gm) \
    asm volatile("cp.async.cg.shared.global [%0], [%1], 16;" :: "r"(sm), "l"(gm))
#define CP_COMMIT() asm volatile("cp.async.commit_group;" ::: "memory")
#define CP_WAIT1()  asm volatile("cp.async.wait_group 1;" ::: "memory")
#define CP_WAIT0()  asm volatile("cp.async.wait_group 0;" ::: "memory")

__device__ __forceinline__ void store_split2(__nv_bfloat16* hi, __nv_bfloat16* lo,
                                             size_t off, float x, float y) {
    __nv_bfloat16 hx = __float2bfloat16(x), hy = __float2bfloat16(y);
    __nv_bfloat16 lx = __float2bfloat16(x - __bfloat162float(hx));
    __nv_bfloat16 ly = __float2bfloat16(y - __bfloat162float(hy));
    __nv_bfloat162 h2; h2.x = hx; h2.y = hy;
    __nv_bfloat162 l2; l2.x = lx; l2.y = ly;
    *(__nv_bfloat162*)(hi + off) = h2;
    *(__nv_bfloat162*)(lo + off) = l2;
}

// ---------------------------------------------------------------------------
// Pre-pass 1 (merged): fp32 -> bf16 hi/lo split for w and r.
// ---------------------------------------------------------------------------
constexpr size_t W_UNITS = (size_t)BSZ * KLEN * DM / 4;
constexpr size_t R_UNITS = (size_t)KLEN * DM / 4;

__global__ void convert_all(const float* __restrict__ w, const float* __restrict__ r) {
    size_t u = (size_t)blockIdx.x * blockDim.x + threadIdx.x;
    const float* s;
    __nv_bfloat16 *hi, *lo;
    size_t base;
    if (u < W_UNITS) { s = w; hi = g_w_hi; lo = g_w_lo; base = u; }
    else             { s = r; hi = g_r_hi; lo = g_r_lo; base = u - W_UNITS; }
    size_t i = base * 4;
    float4 v = *(const float4*)(s + i);
    float vv[4] = {v.x, v.y, v.z, v.w};
    __nv_bfloat16 h[4], l[4];
#pragma unroll
    for (int j = 0; j < 4; j++) {
        h[j] = __float2bfloat16(vv[j]);
        l[j] = __float2bfloat16(vv[j] - __bfloat162float(h[j]));
    }
    *(uint2*)(hi + i) = *(uint2*)h;
    *(uint2*)(lo + i) = *(uint2*)l;
}

// ---------------------------------------------------------------------------
// Pre-pass 2 (merged): all 4 weight transposes. W [K][N] fp32 -> [N][K] bf16.
// ---------------------------------------------------------------------------
__global__ void transpose_all(const float* __restrict__ Wq, const float* __restrict__ Wkv,
                              const float* __restrict__ Wr, const float* __restrict__ Wo) {
    __shared__ float t[32][33];
    int idx = blockIdx.x;
    const float* W;
    __nv_bfloat16 *hi, *lo;
    int N, n0, k0;
    if (idx < 1024) {
        W = Wq; hi = g_wqt_hi; lo = g_wqt_lo; N = DM;
        n0 = (idx & 31) * 32; k0 = (idx >> 5) * 32;
    } else if (idx < 3072) {
        int lidx = idx - 1024;
        W = Wkv; hi = g_wkvt_hi; lo = g_wkvt_lo; N = 2 * DM;
        n0 = (lidx & 63) * 32; k0 = (lidx >> 6) * 32;
    } else if (idx < 4096) {
        int lidx = idx - 3072;
        W = Wr; hi = g_wrt_hi; lo = g_wrt_lo; N = DM;
        n0 = (lidx & 31) * 32; k0 = (lidx >> 5) * 32;
    } else {
        int lidx = idx - 4096;
        W = Wo; hi = g_wot_hi; lo = g_wot_lo; N = DM;
        n0 = (lidx & 31) * 32; k0 = (lidx >> 5) * 32;
    }
    int tx = threadIdx.x, ty = threadIdx.y;
#pragma unroll
    for (int i = 0; i < 4; i++)
        t[ty + 8 * i][tx] = W[(size_t)(k0 + ty + 8 * i) * N + n0 + tx];
    __syncthreads();
#pragma unroll
    for (int i = 0; i < 4; i++) {
        float v = t[tx][ty + 8 * i];
        __nv_bfloat16 h = __float2bfloat16(v);
        __nv_bfloat16 l = __float2bfloat16(v - __bfloat162float(h));
        size_t o = (size_t)(n0 + ty + 8 * i) * DM + k0 + tx;
        hi[o] = h;
        lo[o] = l;
    }
}

// ---------------------------------------------------------------------------
// HMMA split-bf16 GEMM body. 128x128 tile, 8 warps (32x64 warp tile),
// SINGLE 73.7KB buffer -> 2 CTAs/SM; CTA pairs hide each other's loads/syncs.
// mode: 0 -> Qw/Qr(+bias), 1 -> K/V, 2 -> rk, 3 -> fp32 C (d_out)
// ---------------------------------------------------------------------------
constexpr int GEMM_SMEM = 73728;  // 4 arrays * 128 rows * 144B

__device__ __forceinline__ void hgemm_body(
    int mode, int m0, int n0,
    const __nv_bfloat16* __restrict__ Ah, const __nv_bfloat16* __restrict__ Al,
    const __nv_bfloat16* __restrict__ Bh, const __nv_bfloat16* __restrict__ Bl,
    const float* __restrict__ rwb, const float* __restrict__ rrb,
    float* __restrict__ C, char* smc)
{
    const uint32_t sb = smem_to_u32(smc);
    const int tid = threadIdx.x, lane = tid & 31, wid = tid >> 5;
    const int wm = wid >> 1, wn = wid & 1;

    float acc[2][8][4];
#pragma unroll
    for (int a = 0; a < 2; a++)
#pragma unroll
        for (int b = 0; b < 8; b++)
#pragma unroll
            for (int c = 0; c < 4; c++) acc[a][b][c] = 0.f;

#pragma unroll 1
    for (int c = 0; c < 16; c++) {
        const int k0 = c * 64;
#pragma unroll
        for (int it = 0; it < 4; it++) {
            int u = tid + it * 256;
            int row = u >> 3, kk = (u & 7) * 8;
            uint32_t so = row * 144 + kk * 2;
            int am = m0 + row;
            int grow = (mode == 0) ? (((am >> 10) << 11) + QLEN + (am & (QLEN - 1))) : am;
            size_t ao = (size_t)grow * DM + k0 + kk;
            size_t bo = (size_t)(n0 + row) * DM + k0 + kk;
            CP16(sb + so,         Ah + ao);
            CP16(sb + 18432 + so, Al + ao);
            CP16(sb + 36864 + so, Bh + bo);
            CP16(sb + 55296 + so, Bl + bo);
        }
        CP_COMMIT();
        CP_WAIT0();
        __syncthreads();
        const uint32_t aBase = sb + (wm * 32 + (lane & 15)) * 144 + ((lane >> 4) * 8) * 2;
        const uint32_t bBase = sb + 36864 + (wn * 64 + (lane & 7)) * 144
                             + (((lane >> 3) & 1) * 8) * 2;
#pragma unroll
        for (int kk = 0; kk < 4; kk++) {
            uint32_t ah[2][4], al[2][4];
#pragma unroll
            for (int ms = 0; ms < 2; ms++) {
                uint32_t aa = aBase + ms * 16 * 144 + kk * 32;
                ldsm4(ah[ms], aa);
                ldsm4(al[ms], aa + 18432);
            }
#pragma unroll
            for (int ns = 0; ns < 8; ns++) {
                uint32_t ba = bBase + ns * 8 * 144 + kk * 32;
                uint32_t bh2[2], bl2[2];
                ldsm2(bh2, ba);
                ldsm2(bl2, ba + 18432);
                mma16816(acc[0][ns], ah[0], bh2);
                mma16816(acc[1][ns], ah[1], bh2);
                mma16816(acc[0][ns], ah[0], bl2);
                mma16816(acc[1][ns], ah[1], bl2);
                mma16816(acc[0][ns], al[0], bh2);
                mma16816(acc[1][ns], al[1], bh2);
            }
        }
        __syncthreads();
    }

    // epilogue
#pragma unroll
    for (int ms = 0; ms < 2; ms++) {
        int r0 = m0 + wm * 32 + ms * 16 + (lane >> 2);
#pragma unroll
        for (int ns = 0; ns < 8; ns++) {
            int col = n0 + wn * 64 + ns * 8 + (lane & 3) * 2;
#pragma unroll
            for (int h = 0; h < 2; h++) {
                int row = r0 + h * 8;
                float x = acc[ms][ns][h * 2 + 0];
                float y = acc[ms][ns][h * 2 + 1];
                if (mode == 0) {
                    int bb = row >> 10, ii = row & 1023;
                    int head = col >> 6, d = col & 63;
                    size_t off = (((size_t)(bb * NH + head)) * QLEN + ii) * DH + d;
                    store_split2(g_qw_hi, g_qw_lo, off, x + rwb[col], y + rwb[col + 1]);
                    store_split2(g_qr_hi, g_qr_lo, off, x + rrb[col], y + rrb[col + 1]);
                } else if (mode == 1) {
                    int bb = row >> 11, jj = row & 2047;
                    int cc = (col < DM) ? col : col - DM;
                    int head = cc >> 6, d = cc & 63;
                    size_t off = (((size_t)(bb * NH + head)) * KLEN + jj) * DH + d;
                    if (col < DM) store_split2(g_k_hi, g_k_lo, off, x, y);
                    else          store_split2(g_v_hi, g_v_lo, off, x, y);
                } else if (mode == 2) {
                    int head = col >> 6, d = col & 63;
                    size_t off = ((size_t)head * KLEN + row) * DH + d;
                    store_split2(g_rk_hi, g_rk_lo, off, x, y);
                } else {
                    *(float2*)(C + (size_t)row * DM + col) = make_float2(x, y);
                }
            }
        }
    }
}

__global__ void __launch_bounds__(256, 2)
hgemm_proj(const float* __restrict__ rwb, const float* __restrict__ rrb)
{
    extern __shared__ __align__(1024) char smc[];
    int idx = blockIdx.x;
    int mode, m0, n0;
    const __nv_bfloat16 *Ah, *Al, *Bh, *Bl;
    if (idx < 1024) {        // KV: grid 16 x 64
        mode = 1; n0 = (idx & 15) * 128; m0 = (idx >> 4) * 128;
        Ah = g_w_hi; Al = g_w_lo; Bh = g_wkvt_hi; Bl = g_wkvt_lo;
    } else if (idx < 1280) { // Q: grid 8 x 32
        int r = idx - 1024;
        mode = 0; n0 = (r & 7) * 128; m0 = (r >> 3) * 128;
        Ah = g_w_hi; Al = g_w_lo; Bh = g_wqt_hi; Bl = g_wqt_lo;
    } else {                 // R: grid 8 x 16
        int r = idx - 1280;
        mode = 2; n0 = (r & 7) * 128; m0 = (r >> 3) * 128;
        Ah = g_r_hi; Al = g_r_lo; Bh = g_wrt_hi; Bl = g_wrt_lo;
    }
    hgemm_body(mode, m0, n0, Ah, Al, Bh, Bl, rwb, rrb, nullptr, smc);
}

__global__ void __launch_bounds__(256, 2)
hgemm_out(float* __restrict__ C)
{
    extern __shared__ __align__(1024) char smc[];
    hgemm_body(3, blockIdx.y * 128, blockIdx.x * 128,
               g_av_hi, g_av_lo, g_wot_hi, g_wot_lo, nullptr, nullptr, C, smc);
}

// ---------------------------------------------------------------------------
// HMMA flash attention, BI=64 query rows x BJ=128 key cols per tile.
// Swizzled 128B rows (no padding) for Q/K/V/RW. Region-phased cp.async:
// K/RW(t+1) prefetched after scatter (regions dead post-MMA), V(t+1) after PV.
// T window = 192 cols (vs 2x64-tiles' 2x128): -25% T flops.
// ---------------------------------------------------------------------------
constexpr int oKH = 0, oKL = 16384, oVH = 32768, oVL = 49152;   // 128 x 128B
constexpr int oRWH = 65536, oRWL = 90112;                       // 192 x 128B
constexpr int sQWH = 114688, sQWL = 122880, sQRH = 131072, sQRL = 139264; // 64x128B
constexpr int sS = 147456;      // 64 x 132 f32; col 128 = CO, col 129 = LS
constexpr int sPH = 181248, sPL = 198656;  // 64 x 136 bf16 (272B rows)
constexpr int ATTN_SMEM = 216064;

__global__ void __launch_bounds__(256, 1) attn3()
{
    extern __shared__ __align__(1024) char smc[];
    const uint32_t sb = smem_to_u32(smc);
    const int tid = threadIdx.x, lane = tid & 31, wid = tid >> 5;
    const int wm = wid >> 1, wn = wid & 1;
    const int itile = 15 - (blockIdx.x & 15);  // heavy tiles first
    const int bh = blockIdx.x >> 4;
    const int head = bh & 15, bb = bh >> 4;
    const int i0 = itile * 64;
    const int ntiles = (i0 + 1215) >> 7;       // ceil((i0+63+1024+1)/128)

    auto issue_krw = [&](int t) {
        const int j0 = t * 128;
#pragma unroll
        for (int it = 0; it < 4; it++) {       // K: 128 rows x 8 granules
            int u = tid + it * 256;
            int row = u >> 3, g = u & 7;
            uint32_t so = swz((uint32_t)(row * 128 + g * 16));
            size_t off = ((size_t)bh * KLEN + j0 + row) * DH + g * 8;
            CP16(sb + oKH + so, g_k_hi + off);
            CP16(sb + oKL + so, g_k_lo + off);
        }
        const int dbase = j0 - i0 + 960;
#pragma unroll
        for (int it = 0; it < 6; it++) {       // RW: 192 rows x 8 granules
            int u = tid + it * 256;
            int row = u >> 3, g = u & 7;
            int dr = dbase + row;
            dr = dr < 0 ? 0 : (dr > KLEN - 1 ? KLEN - 1 : dr);  // OOB masked later
            uint32_t so = swz((uint32_t)(row * 128 + g * 16));
            size_t off = ((size_t)head * KLEN + dr) * DH + g * 8;
            CP16(sb + oRWH + so, g_rk_hi + off);
            CP16(sb + oRWL + so, g_rk_lo + off);
        }
        CP_COMMIT();
    };
    auto issue_v = [&](int t) {
        const int j0 = t * 128;
#pragma unroll
        for (int it = 0; it < 4; it++) {
            int u = tid + it * 256;
            int row = u >> 3, g = u & 7;
            uint32_t so = swz((uint32_t)(row * 128 + g * 16));
            size_t off = ((size_t)bh * KLEN + j0 + row) * DH + g * 8;
            CP16(sb + oVH + so, g_v_hi + off);
            CP16(sb + oVL + so, g_v_lo + off);
        }
        CP_COMMIT();
    };

    // prologue: KRW(0) [group], Q + V(0) [group], wait all
    issue_krw(0);
#pragma unroll
    for (int it = 0; it < 2; it++) {           // Q: 64 rows x 8 granules x 4 tensors
        int u = tid + it * 256;
        int row = u >> 3, g = u & 7;
        uint32_t so = swz((uint32_t)(row * 128 + g * 16));
        size_t off = ((size_t)bh * QLEN + i0 + row) * DH + g * 8;
        CP16(sb + sQWH + so, g_qw_hi + off);
        CP16(sb + sQWL + so, g_qw_lo + off);
        CP16(sb + sQRH + so, g_qr_hi + off);
        CP16(sb + sQRL + so, g_qr_lo + off);
    }
    issue_v(0);
    CP_WAIT0();
    __syncthreads();

    float o[4][4];
#pragma unroll
    for (int a = 0; a < 4; a++)
#pragma unroll
        for (int b = 0; b < 4; b++) o[a][b] = 0.f;
    float mrow = -3.0e38f, lrow = 0.f;
    const int srow = tid >> 2, sc0 = (tid & 3) * 32;
    float* Sf = (float*)(smc + sS);

#pragma unroll 1
    for (int t = 0; t < ntiles; t++) {
        const int j0 = t * 128;
        if (t > 0) { CP_WAIT1(); }   // completes KRW(t); V(t) may still fly
        __syncthreads();

        // ---- phase A: S = Qw@K^T (64x128), T = Qr@Rw^T (64x192) ----
        float sacc[8][4], tacc[12][4];
#pragma unroll
        for (int a = 0; a < 8; a++)
#pragma unroll
            for (int b = 0; b < 4; b++) sacc[a][b] = 0.f;
#pragma unroll
        for (int a = 0; a < 12; a++)
#pragma unroll
            for (int b = 0; b < 4; b++) tacc[a][b] = 0.f;
        {
            const int qrow = wm * 16 + (lane & 15);
            const int qg = lane >> 4;
            const int brow = (lane & 7) + ((lane >> 4) << 3);
            const int bg = (lane >> 3) & 1;
#pragma unroll
            for (int kk = 0; kk < 4; kk++) {
                uint32_t qo = swz((uint32_t)(qrow * 128 + qg * 16 + kk * 32));
                uint32_t qwh[4], qwl[4], qrh[4], qrl[4];
                ldsm4(qwh, sb + sQWH + qo);
                ldsm4(qwl, sb + sQWL + qo);
                ldsm4(qrh, sb + sQRH + qo);
                ldsm4(qrl, sb + sQRL + qo);
#pragma unroll
                for (int np = 0; np < 4; np++) {   // K pairs: ns = 2np, 2np+1
                    uint32_t ko = swz((uint32_t)((wn * 64 + np * 16 + brow) * 128
                                                 + bg * 16 + kk * 32));
                    uint32_t bh4[4], bl4[4];
                    ldsm4(bh4, sb + oKH + ko);
                    ldsm4(bl4, sb + oKL + ko);
                    mma16816(sacc[2 * np],     qwh, bh4);
                    mma16816(sacc[2 * np + 1], qwh, bh4 + 2);
                    mma16816(sacc[2 * np],     qwh, bl4);
                    mma16816(sacc[2 * np + 1], qwh, bl4 + 2);
                    mma16816(sacc[2 * np],     qwl, bh4);
                    mma16816(sacc[2 * np + 1], qwl, bh4 + 2);
                }
#pragma unroll
                for (int np = 0; np < 6; np++) {   // RW pairs
                    uint32_t ro = swz((uint32_t)((wn * 96 + np * 16 + brow) * 128
                                                 + bg * 16 + kk * 32));
                    uint32_t bh4[4], bl4[4];
                    ldsm4(bh4, sb + oRWH + ro);
                    ldsm4(bl4, sb + oRWL + ro);
                    mma16816(tacc[2 * np],     qrh, bh4);
                    mma16816(tacc[2 * np + 1], qrh, bh4 + 2);
                    mma16816(tacc[2 * np],     qrh, bl4);
                    mma16816(tacc[2 * np + 1], qrh, bl4 + 2);
                    mma16816(tacc[2 * np],     qrl, bh4);
                    mma16816(tacc[2 * np + 1], qrl, bh4 + 2);
                }
            }
        }
        // write S fragments
        {
            int r0 = wm * 16 + (lane >> 2);
#pragma unroll
            for (int ns = 0; ns < 8; ns++) {
                int c = wn * 64 + ns * 8 + (lane & 3) * 2;
                *(float2*)&Sf[r0 * 132 + c]       = make_float2(sacc[ns][0], sacc[ns][1]);
                *(float2*)&Sf[(r0 + 8) * 132 + c] = make_float2(sacc[ns][2], sacc[ns][3]);
            }
        }
        __syncthreads();

        // ---- phase B: scatter-add T frags into S at c = c' + r - 63 ----
        {
            int r0 = wm * 16 + (lane >> 2);
            int cb = wn * 96 + (lane & 3) * 2 - 63;
#pragma unroll
            for (int ns = 0; ns < 12; ns++) {
#pragma unroll
                for (int h = 0; h < 2; h++) {
                    int r = r0 + h * 8;
                    int c0 = cb + ns * 8 + r;
                    if (c0 >= 0 && c0 < 128) Sf[r * 132 + c0] += tacc[ns][h * 2 + 0];
                    int c1 = c0 + 1;
                    if (c1 >= 0 && c1 < 128) Sf[r * 132 + c1] += tacc[ns][h * 2 + 1];
                }
            }
        }
        __syncthreads();
        if (t + 1 < ntiles) issue_krw(t + 1);  // K/RW regions dead -> prefetch

        // ---- phase C: softmax (4 threads per row, 32 cols each) ----
        {
            const int gi = i0 + srow;
            float sv[32];
            float mt = -3.0e38f;
#pragma unroll
            for (int c2 = 0; c2 < 32; c2++) {
                int c = sc0 + c2;
                float s = Sf[srow * 132 + c] * 0.125f;
                s = ((j0 + c) > gi + 1024) ? -1.0e30f : s;
                sv[c2] = s;
                mt = fmaxf(mt, s);
            }
            mt = fmaxf(mt, __shfl_xor_sync(0xffffffffu, mt, 1));
            mt = fmaxf(mt, __shfl_xor_sync(0xffffffffu, mt, 2));
            float mn = fmaxf(mrow, mt);
            float co = __expf(mrow - mn);
            mrow = mn;
            float rs = 0.f;
            __nv_bfloat16* Ph = (__nv_bfloat16*)(smc + sPH);
            __nv_bfloat16* Pl = (__nv_bfloat16*)(smc + sPL);
#pragma unroll
            for (int c2 = 0; c2 < 32; c2 += 2) {
                float p0 = __expf(sv[c2] - mn);
                float p1 = __expf(sv[c2 + 1] - mn);
                rs += p0 + p1;
                __nv_bfloat16 h0 = __float2bfloat16(p0), h1 = __float2bfloat16(p1);
                __nv_bfloat162 h2; h2.x = h0; h2.y = h1;
                __nv_bfloat162 l2;
                l2.x = __float2bfloat16(p0 - __bfloat162float(h0));
                l2.y = __float2bfloat16(p1 - __bfloat162float(h1));
                int c = sc0 + c2;
                *(__nv_bfloat162*)&Ph[srow * 136 + c] = h2;
                *(__nv_bfloat162*)&Pl[srow * 136 + c] = l2;
            }
            rs += __shfl_xor_sync(0xffffffffu, rs, 1);
            rs += __shfl_xor_sync(0xffffffffu, rs, 2);
            lrow = lrow * co + rs;
            if ((tid & 3) == 0) Sf[srow * 132 + 128] = co;
        }
        if (t + 1 < ntiles) { CP_WAIT1(); } else { CP_WAIT0(); }  // completes V(t)
        __syncthreads();

        // ---- phase D: O = O*co + P @ V  (k = 128 over 8 kk steps) ----
        {
            float co0 = Sf[(wm * 16 + (lane >> 2)) * 132 + 128];
            float co1 = Sf[(wm * 16 + (lane >> 2) + 8) * 132 + 128];
#pragma unroll
            for (int ns = 0; ns < 4; ns++) {
                o[ns][0] *= co0; o[ns][1] *= co0;
                o[ns][2] *= co1; o[ns][3] *= co1;
            }
            const uint32_t pb = sb + sPH + (wm * 16 + (lane & 15)) * 272
                              + (lane >> 4) * 16;
#pragma unroll
            for (int kk = 0; kk < 8; kk++) {
                uint32_t pah[4], pal[4];
                ldsm4(pah, pb + kk * 32);
                ldsm4(pal, pb + 17408 + kk * 32);
                uint32_t vh[4][2], vl[4][2];
#pragma unroll
                for (int ns = 0; ns < 4; ns++) {
                    uint32_t vo = swz((uint32_t)((kk * 16 + (lane & 15)) * 128
                                                 + (wn * 32 + ns * 8) * 2));
                    ldsm2t(vh[ns], sb + oVH + vo);
                    ldsm2t(vl[ns], sb + oVL + vo);
                }
#pragma unroll
                for (int ns = 0; ns < 4; ns++) mma16816(o[ns], pah, vh[ns]);
#pragma unroll
                for (int ns = 0; ns < 4; ns++) mma16816(o[ns], pah, vl[ns]);
#pragma unroll
                for (int ns = 0; ns < 4; ns++) mma16816(o[ns], pal, vh[ns]);
            }
        }
        __syncthreads();                       // V & P fully consumed
        if (t + 1 < ntiles) issue_v(t + 1);
    }

    // ---- finalize: O / l, split to bf16, write [b, i, head*64+d] ----
    if ((tid & 3) == 0) Sf[srow * 132 + 129] = lrow;
    __syncthreads();
    {
        float li0 = 1.f / Sf[(wm * 16 + (lane >> 2)) * 132 + 129];
        float li1 = 1.f / Sf[(wm * 16 + (lane >> 2) + 8) * 132 + 129];
        int gi0 = i0 + wm * 16 + (lane >> 2);
#pragma unroll
        for (int ns = 0; ns < 4; ns++) {
            int d = wn * 32 + ns * 8 + (lane & 3) * 2;
            size_t off0 = ((size_t)bb * QLEN + gi0) * DM + head * DH + d;
            store_split2(g_av_hi, g_av_lo, off0, o[ns][0] * li0, o[ns][1] * li0);
            store_split2(g_av_hi, g_av_lo, off0 + 8 * DM, o[ns][2] * li1, o[ns][3] * li1);
        }
    }
}

// ---------------------------------------------------------------------------
extern "C" void kernel_launch(void* const* d_in, const int* in_sizes, int n_in,
                              void* d_out, int out_size)
{
    const float* w   = (const float*)d_in[0];
    const float* r   = (const float*)d_in[1];
    const float* rwb = (const float*)d_in[2];
    const float* rrb = (const float*)d_in[3];
    const float* Wq  = (const float*)d_in[4];
    const float* Wkv = (const float*)d_in[5];
    const float* Wr  = (const float*)d_in[6];
    const float* Wo  = (const float*)d_in[7];
    float* out = (float*)d_out;

    // merged pre-passes
    convert_all<<<(int)((W_UNITS + R_UNITS) / 256), 256>>>(w, r);
    transpose_all<<<5120, dim3(32, 8)>>>(Wq, Wkv, Wr, Wo);

    cudaFuncSetAttribute(hgemm_proj, cudaFuncAttributeMaxDynamicSharedMemorySize, GEMM_SMEM);
    cudaFuncSetAttribute(hgemm_out,  cudaFuncAttributeMaxDynamicSharedMemorySize, GEMM_SMEM);
    cudaFuncSetAttribute(attn3, cudaFuncAttributeMaxDynamicSharedMemorySize, ATTN_SMEM);

    // merged projections: 1024 (KV) + 256 (Q) + 128 (R) CTAs, 2 CTAs/SM
    hgemm_proj<<<1408, 256, GEMM_SMEM>>>(rwb, rrb);

    // fused relative attention (BI=64, BJ=128)
    attn3<<<BSZ * NH * (QLEN / 64), 256, ATTN_SMEM>>>();

    // output projection
    hgemm_out<<<dim3(DM / 128, (BSZ * QLEN) / 128), 256, GEMM_SMEM>>>(out);
}